// round 13
// baseline (speedup 1.0000x reference)
#include <cuda_runtime.h>
#include <cuda_bf16.h>
#include <cstdint>
#include <cstddef>

#define C_DIM 256
#define L_DIM 4096
#define N_DIM 64
#define M_TOT (N_DIM * L_DIM)   // 262144
#define EPSV 1e-3f

// ---------------- scratch (device globals) ----------------
__device__ __nv_bfloat16 g_Wb[C_DIM * C_DIM];   // bf16 (wm - I)
__device__ float g_mean[C_DIM];                 // raw channel sums
__device__ float g_gram[C_DIM * C_DIM];         // raw X X^T sums (Q00, Q10, Q11 used)
__device__ float g_A[C_DIM * C_DIM];
__device__ float g_A2[C_DIM * C_DIM];           // atomic accum: A@A
__device__ float g_bias[C_DIM];
__device__ float g_scal[1];                     // rsqrt(s)

// ---------------- low-level helpers ----------------
__device__ __forceinline__ uint32_t smem_u32(const void* p) {
    return (uint32_t)__cvta_generic_to_shared(p);
}
__device__ __forceinline__ void cp16(uint32_t saddr, const void* g) {
    asm volatile("cp.async.cg.shared.global [%0], [%1], 16;\n" :: "r"(saddr), "l"(g));
}
__device__ __forceinline__ void cp_commit() { asm volatile("cp.async.commit_group;\n"); }
template<int N> __device__ __forceinline__ void cp_wait() {
    asm volatile("cp.async.wait_group %0;\n" :: "n"(N));
}
__device__ __forceinline__ void ldsm4(uint32_t r[4], uint32_t a) {
    asm volatile("ldmatrix.sync.aligned.m8n8.x4.shared.b16 {%0,%1,%2,%3}, [%4];"
                 : "=r"(r[0]), "=r"(r[1]), "=r"(r[2]), "=r"(r[3]) : "r"(a));
}
__device__ __forceinline__ void ldsm2(uint32_t r[2], uint32_t a) {
    asm volatile("ldmatrix.sync.aligned.m8n8.x2.shared.b16 {%0,%1}, [%2];"
                 : "=r"(r[0]), "=r"(r[1]) : "r"(a));
}
__device__ __forceinline__ void ldsm2t(uint32_t r[2], uint32_t a) {
    asm volatile("ldmatrix.sync.aligned.m8n8.x2.trans.shared.b16 {%0,%1}, [%2];"
                 : "=r"(r[0]), "=r"(r[1]) : "r"(a));
}
__device__ __forceinline__ void mma_bf16(float d[4], const uint32_t a[4], const uint32_t b[2]) {
    asm volatile("mma.sync.aligned.m16n8k16.row.col.f32.bf16.bf16.f32 "
                 "{%0,%1,%2,%3}, {%4,%5,%6,%7}, {%8,%9}, {%0,%1,%2,%3};"
                 : "+f"(d[0]), "+f"(d[1]), "+f"(d[2]), "+f"(d[3])
                 : "r"(a[0]), "r"(a[1]), "r"(a[2]), "r"(a[3]), "r"(b[0]), "r"(b[1]));
}
__device__ __forceinline__ uint32_t pk2(float x, float y) {
    __nv_bfloat162 h = __floats2bfloat162_rn(x, y);
    return *(uint32_t*)&h;
}

// ---------------- zero accumulators ----------------
__global__ void zero_kernel() {
    int idx = blockIdx.x * 256 + threadIdx.x;
    g_gram[idx] = 0.f;
    g_A2[idx] = 0.f;
    if (idx < C_DIM) { g_mean[idx] = 0.f; g_bias[idx] = 0.f; }
}

// ---------------- gramL: left half (rows 0..255) x (cols 0..127), ONE shared tile ----------------
__global__ __launch_bounds__(512, 1) void gramL_kernel(const float* __restrict__ X) {
    __shared__ __align__(16) __nv_bfloat16 Ts[2][256][40];
    const int n = blockIdx.x, zh = blockIdx.y;
    const int tid = threadIdx.x, wid = tid >> 5, lane = tid & 31;
    const int m0 = (wid >> 2) * 64, n0 = (wid & 3) * 32;
    const int row = tid >> 1, seg = (tid & 1) * 16;

    const float* Ag = X + ((size_t)(n * C_DIM + row)) * L_DIM + zh * 1024 + seg;

    float acc[4][4][4];
#pragma unroll
    for (int i = 0; i < 4; i++)
#pragma unroll
        for (int j = 0; j < 4; j++)
#pragma unroll
            for (int r = 0; r < 4; r++) acc[i][j][r] = 0.f;
    float msum = 0.f;
    float4 pa[4];

#pragma unroll
    for (int q = 0; q < 4; q++) pa[q] = *(const float4*)(Ag + q * 4);
    msum += (pa[0].x + pa[0].y + pa[0].z + pa[0].w) + (pa[1].x + pa[1].y + pa[1].z + pa[1].w)
          + (pa[2].x + pa[2].y + pa[2].z + pa[2].w) + (pa[3].x + pa[3].y + pa[3].z + pa[3].w);
    *(uint4*)&Ts[0][row][seg] = make_uint4(pk2(pa[0].x, pa[0].y), pk2(pa[0].z, pa[0].w),
                                           pk2(pa[1].x, pa[1].y), pk2(pa[1].z, pa[1].w));
    *(uint4*)&Ts[0][row][seg + 8] = make_uint4(pk2(pa[2].x, pa[2].y), pk2(pa[2].z, pa[2].w),
                                               pk2(pa[3].x, pa[3].y), pk2(pa[3].z, pa[3].w));

#pragma unroll 1
    for (int c = 0; c < 32; c++) {
        __syncthreads();
        const bool more = (c + 1 < 32);
        if (more) {
#pragma unroll
            for (int q = 0; q < 4; q++) pa[q] = *(const float4*)(Ag + (c + 1) * 32 + q * 4);
        }
        const int buf = c & 1;
#pragma unroll
        for (int ks = 0; ks < 2; ks++) {
            uint32_t af[4][4], bq[4][2];
#pragma unroll
            for (int i = 0; i < 4; i++)
                ldsm4(af[i], smem_u32(&Ts[buf][m0 + i * 16 + (lane & 15)][ks * 16 + ((lane >> 4) << 3)]));
#pragma unroll
            for (int j = 0; j < 4; j++)
                ldsm2(bq[j], smem_u32(&Ts[buf][n0 + j * 8 + (lane & 7)][ks * 16 + (lane & 8)]));
#pragma unroll
            for (int i = 0; i < 4; i++)
#pragma unroll
                for (int j = 0; j < 4; j++) mma_bf16(acc[i][j], af[i], bq[j]);
        }
        if (more) {
            const int nb = (c + 1) & 1;
            msum += (pa[0].x + pa[0].y + pa[0].z + pa[0].w) + (pa[1].x + pa[1].y + pa[1].z + pa[1].w)
                  + (pa[2].x + pa[2].y + pa[2].z + pa[2].w) + (pa[3].x + pa[3].y + pa[3].z + pa[3].w);
            *(uint4*)&Ts[nb][row][seg] = make_uint4(pk2(pa[0].x, pa[0].y), pk2(pa[0].z, pa[0].w),
                                                    pk2(pa[1].x, pa[1].y), pk2(pa[1].z, pa[1].w));
            *(uint4*)&Ts[nb][row][seg + 8] = make_uint4(pk2(pa[2].x, pa[2].y), pk2(pa[2].z, pa[2].w),
                                                        pk2(pa[3].x, pa[3].y), pk2(pa[3].z, pa[3].w));
        }
    }

    atomicAdd(&g_mean[row], msum);

    const int r = lane >> 2, cpr = (lane & 3) * 2;
#pragma unroll
    for (int i = 0; i < 4; i++)
#pragma unroll
        for (int j = 0; j < 4; j++) {
            int gi = m0 + i * 16 + r;
            int gj = n0 + j * 8 + cpr;
            atomicAdd(&g_gram[gi * C_DIM + gj], acc[i][j][0]);
            atomicAdd(&g_gram[gi * C_DIM + gj + 1], acc[i][j][1]);
            atomicAdd(&g_gram[(gi + 8) * C_DIM + gj], acc[i][j][2]);
            atomicAdd(&g_gram[(gi + 8) * C_DIM + gj + 1], acc[i][j][3]);
        }
}

// ---------------- gramD: Q11 diagonal block (rows/cols 128..255), A=B one tile ----------------
__global__ __launch_bounds__(256, 2) void gramD_kernel(const float* __restrict__ X) {
    __shared__ __align__(16) __nv_bfloat16 Ts[2][128][40];
    const int n = blockIdx.x, zh = blockIdx.y;
    const int tid = threadIdx.x, wid = tid >> 5, lane = tid & 31;
    const int m0 = (wid >> 2) * 64, n0 = (wid & 3) * 32;
    const int row = tid >> 1, seg = (tid & 1) * 16;

    const float* Ag = X + ((size_t)(n * C_DIM + 128 + row)) * L_DIM + zh * 1024 + seg;

    float acc[4][4][4];
#pragma unroll
    for (int i = 0; i < 4; i++)
#pragma unroll
        for (int j = 0; j < 4; j++)
#pragma unroll
            for (int r = 0; r < 4; r++) acc[i][j][r] = 0.f;
    float4 pa[4];

#pragma unroll
    for (int q = 0; q < 4; q++) pa[q] = *(const float4*)(Ag + q * 4);
    *(uint4*)&Ts[0][row][seg] = make_uint4(pk2(pa[0].x, pa[0].y), pk2(pa[0].z, pa[0].w),
                                           pk2(pa[1].x, pa[1].y), pk2(pa[1].z, pa[1].w));
    *(uint4*)&Ts[0][row][seg + 8] = make_uint4(pk2(pa[2].x, pa[2].y), pk2(pa[2].z, pa[2].w),
                                               pk2(pa[3].x, pa[3].y), pk2(pa[3].z, pa[3].w));

#pragma unroll 1
    for (int c = 0; c < 32; c++) {
        __syncthreads();
        const bool more = (c + 1 < 32);
        if (more) {
#pragma unroll
            for (int q = 0; q < 4; q++) pa[q] = *(const float4*)(Ag + (c + 1) * 32 + q * 4);
        }
        const int buf = c & 1;
#pragma unroll
        for (int ks = 0; ks < 2; ks++) {
            uint32_t af[4][4], bq[4][2];
#pragma unroll
            for (int i = 0; i < 4; i++)
                ldsm4(af[i], smem_u32(&Ts[buf][m0 + i * 16 + (lane & 15)][ks * 16 + ((lane >> 4) << 3)]));
#pragma unroll
            for (int j = 0; j < 4; j++)
                ldsm2(bq[j], smem_u32(&Ts[buf][n0 + j * 8 + (lane & 7)][ks * 16 + (lane & 8)]));
#pragma unroll
            for (int i = 0; i < 4; i++)
#pragma unroll
                for (int j = 0; j < 4; j++) mma_bf16(acc[i][j], af[i], bq[j]);
        }
        if (more) {
            const int nb = (c + 1) & 1;
            *(uint4*)&Ts[nb][row][seg] = make_uint4(pk2(pa[0].x, pa[0].y), pk2(pa[0].z, pa[0].w),
                                                    pk2(pa[1].x, pa[1].y), pk2(pa[1].z, pa[1].w));
            *(uint4*)&Ts[nb][row][seg + 8] = make_uint4(pk2(pa[2].x, pa[2].y), pk2(pa[2].z, pa[2].w),
                                                        pk2(pa[3].x, pa[3].y), pk2(pa[3].z, pa[3].w));
        }
    }

    const int r = lane >> 2, cpr = (lane & 3) * 2;
#pragma unroll
    for (int i = 0; i < 4; i++)
#pragma unroll
        for (int j = 0; j < 4; j++) {
            int gi = 128 + m0 + i * 16 + r;
            int gj = 128 + n0 + j * 8 + cpr;
            atomicAdd(&g_gram[gi * C_DIM + gj], acc[i][j][0]);
            atomicAdd(&g_gram[gi * C_DIM + gj + 1], acc[i][j][1]);
            atomicAdd(&g_gram[(gi + 8) * C_DIM + gj], acc[i][j][2]);
            atomicAdd(&g_gram[(gi + 8) * C_DIM + gj + 1], acc[i][j][3]);
        }
}

// ---------------- buildA (fused trace): quadrants Q00, Q10 (mirror->Q01), Q11 ----------------
__global__ void buildA_kernel() {
    __shared__ float red[256];
    const float invm = 1.f / (float)M_TOT;
    int t = threadIdx.x;
    {
        float mu = g_mean[t] * invm;
        red[t] = g_gram[t * (C_DIM + 1)] * invm - mu * mu + EPSV;
    }
    __syncthreads();
    for (int s = 128; s > 0; s >>= 1) {
        if (t < s) red[t] += red[t + s];
        __syncthreads();
    }
    float sv = red[0] / (float)C_DIM;
    float invs = 1.f / sv;
    if (blockIdx.x == 0 && t == 0) g_scal[0] = rsqrtf(sv);

    int base = blockIdx.x * 1024 + t * 4;
#pragma unroll
    for (int u = 0; u < 4; u++) {
        int idx = base + u;
        int q = idx >> 14, rr = idx & 16383;
        int i, j;
        if (q == 0)      { i = rr >> 7;         j = rr & 127; }
        else if (q == 1) { i = 128 + (rr >> 7); j = rr & 127; }
        else             { i = 128 + (rr >> 7); j = 128 + (rr & 127); }
        float sig = g_gram[i * C_DIM + j] * invm - (g_mean[i] * invm) * (g_mean[j] * invm);
        if (i == j) sig += EPSV;
        float v = sig * invs - ((i == j) ? 1.f : 0.f);
        g_A[i * C_DIM + j] = v;
        if (q == 1) g_A[j * C_DIM + i] = v;
    }
}

// ---------------- small fp32 64x64-tile GEMM core, K range [kb, ke) ----------------
__device__ __forceinline__ void small_gemm64(const float* __restrict__ A, const float* __restrict__ B,
                                             float acc[4][4], int i0, int j0, int kb, int ke) {
    __shared__ float As[16][68];
    __shared__ float Bs[16][68];
    const int tid = threadIdx.x;
    const int tx = tid & 15, ty = tid >> 4;
    const int arow = tid >> 2, akq = (tid & 3) * 4;
    for (int k0 = kb; k0 < ke; k0 += 16) {
        __syncthreads();
        float4 va = *(const float4*)&A[(i0 + arow) * C_DIM + k0 + akq];
        As[akq + 0][arow] = va.x; As[akq + 1][arow] = va.y;
        As[akq + 2][arow] = va.z; As[akq + 3][arow] = va.w;
        float4 vb = *(const float4*)&B[(k0 + ty) * C_DIM + j0 + tx * 4];
        *(float4*)&Bs[ty][tx * 4] = vb;
        __syncthreads();
#pragma unroll
        for (int k = 0; k < 16; k++) {
            float4 a = *(const float4*)&As[k][ty * 4];
            float4 b = *(const float4*)&Bs[k][tx * 4];
            float av[4] = {a.x, a.y, a.z, a.w};
            float bv[4] = {b.x, b.y, b.z, b.w};
#pragma unroll
            for (int r = 0; r < 4; r++)
#pragma unroll
                for (int c = 0; c < 4; c++) acc[r][c] = fmaf(av[r], bv[c], acc[r][c]);
        }
    }
}

// ---------------- A2 = A@A, split-K x4, atomic accumulate ----------------
__global__ void pgemmA2_kernel() {
    int i0 = blockIdx.y * 64, j0 = blockIdx.x * 64, z = blockIdx.z;
    float acc[4][4] = {};
    small_gemm64(g_A, g_A, acc, i0, j0, z * 64, z * 64 + 64);
    int tx = threadIdx.x & 15, ty = threadIdx.x >> 4;
#pragma unroll
    for (int r = 0; r < 4; r++)
#pragma unroll
        for (int c = 0; c < 4; c++)
            atomicAdd(&g_A2[(i0 + ty * 4 + r) * C_DIM + j0 + tx * 4 + c], acc[r][c]);
}

// ---------------- final: acc = Q@A2 with Q built in the A-tile load ----------------
__global__ void final_gemm_kernel() {
    const float c1 = -0.5f, c2 = 0.375f, c3 = -0.3125f, c4 = 0.2734375f;
    __shared__ float As[16][68];
    __shared__ float Bs[16][68];
    int i0 = blockIdx.y * 64, j0 = blockIdx.x * 64;
    const int tid = threadIdx.x;
    const int tx = tid & 15, ty = tid >> 4;
    const int arow = tid >> 2, akq = (tid & 3) * 4;
    float acc[4][4] = {};

    for (int k0 = 0; k0 < C_DIM; k0 += 16) {
        __syncthreads();
        int gi = i0 + arow, gk = k0 + akq;
        float4 a1 = *(const float4*)&g_A[gi * C_DIM + gk];
        float4 a2 = *(const float4*)&g_A2[gi * C_DIM + gk];
        As[akq + 0][arow] = c3 * a1.x + c4 * a2.x + ((gi == gk + 0) ? c2 : 0.f);
        As[akq + 1][arow] = c3 * a1.y + c4 * a2.y + ((gi == gk + 1) ? c2 : 0.f);
        As[akq + 2][arow] = c3 * a1.z + c4 * a2.z + ((gi == gk + 2) ? c2 : 0.f);
        As[akq + 3][arow] = c3 * a1.w + c4 * a2.w + ((gi == gk + 3) ? c2 : 0.f);
        float4 vb = *(const float4*)&g_A2[(k0 + ty) * C_DIM + j0 + tx * 4];
        *(float4*)&Bs[ty][tx * 4] = vb;
        __syncthreads();
#pragma unroll
        for (int k = 0; k < 16; k++) {
            float4 a = *(const float4*)&As[k][ty * 4];
            float4 b = *(const float4*)&Bs[k][tx * 4];
            float av[4] = {a.x, a.y, a.z, a.w};
            float bv[4] = {b.x, b.y, b.z, b.w};
#pragma unroll
            for (int r = 0; r < 4; r++)
#pragma unroll
                for (int c = 0; c < 4; c++) acc[r][c] = fmaf(av[r], bv[c], acc[r][c]);
        }
    }

    float rs = g_scal[0];
    const float invm = 1.f / (float)M_TOT;
#pragma unroll
    for (int r = 0; r < 4; r++) {
        int gi = i0 + ty * 4 + r;
        float bsum = 0.f;
#pragma unroll
        for (int c = 0; c < 4; c++) {
            int gj = j0 + tx * 4 + c;
            float d = (gi == gj) ? 1.f : 0.f;
            float w = rs * (d + c1 * g_A[gi * C_DIM + gj] + acc[r][c]);
            g_Wb[gi * C_DIM + gj] = __float2bfloat16(w - d);
            bsum += w * (g_mean[gj] * invm);
        }
        atomicAdd(&g_bias[gi], bsum);
    }
}

// ---------------- apply: out = (wm-I)@bf16(X) + X - bias ; M=256 tile, K-chunk 64 ----------------
#define A_STR 72
#define APPLY_SMEM (2 * 256 * A_STR * 2 + 2 * 64 * 136 * 2)   // 73728 + 34816 = 108544 bytes
__global__ __launch_bounds__(512, 1) void apply_kernel(const float* __restrict__ X,
                                                       float* __restrict__ out) {
    extern __shared__ __align__(16) char sm[];
    __nv_bfloat16 (*As)[A_STR] = (__nv_bfloat16 (*)[A_STR])sm;                        // [2*256][72]
    __nv_bfloat16 (*Bs)[136] = (__nv_bfloat16 (*)[136])(sm + 2 * 256 * A_STR * 2);    // [2*64][136]
    const int l0 = blockIdx.x * 128, n = blockIdx.y;
    const int tid = threadIdx.x, wid = tid >> 5, lane = tid & 31;
    const int m0 = (wid >> 2) * 64, n0 = (wid & 3) * 32;
    const int arow = tid >> 1, aseg = (tid & 1) * 32;   // 256 rows x 2 half-rows of 32 k
    const int brow = tid >> 3, bcol = (tid & 7) * 16;   // 64 k-rows x 128 l (16 each)

    const __nv_bfloat16* Ag = g_Wb + arow * C_DIM + aseg;
    const float* Bg = X + ((size_t)(n * C_DIM + brow)) * L_DIM + l0 + bcol;

    float acc[4][4][4];
#pragma unroll
    for (int i = 0; i < 4; i++)
#pragma unroll
        for (int j = 0; j < 4; j++)
#pragma unroll
            for (int r = 0; r < 4; r++) acc[i][j][r] = 0.f;

    uint32_t sA0 = smem_u32(&As[arow][aseg]);
    const uint32_t aStride = 256 * A_STR * 2;
    float4 pb[4];

    // prologue: A0 cp.async (32 k = 64B = 4x cp16), B0 LDG + convert + STS
#pragma unroll
    for (int q = 0; q < 4; q++) cp16(sA0 + q * 16, Ag + q * 8);
#pragma unroll
    for (int q = 0; q < 4; q++) pb[q] = *(const float4*)(Bg + q * 4);
    cp_commit();
    *(uint4*)&Bs[brow][bcol] = make_uint4(pk2(pb[0].x, pb[0].y), pk2(pb[0].z, pb[0].w),
                                          pk2(pb[1].x, pb[1].y), pk2(pb[1].z, pb[1].w));
    *(uint4*)&Bs[brow][bcol + 8] = make_uint4(pk2(pb[2].x, pb[2].y), pk2(pb[2].z, pb[2].w),
                                              pk2(pb[3].x, pb[3].y), pk2(pb[3].z, pb[3].w));

#pragma unroll 1
    for (int c = 0; c < 4; c++) {
        const bool more = (c + 1 < 4);
        if (more) {
            int k0n = (c + 1) * 64;
            int nb = (c + 1) & 1;
#pragma unroll
            for (int q = 0; q < 4; q++) cp16(sA0 + nb * aStride + q * 16, Ag + k0n + q * 8);
#pragma unroll
            for (int q = 0; q < 4; q++) pb[q] = *(const float4*)(Bg + (size_t)k0n * L_DIM + q * 4);
            cp_commit();
            cp_wait<1>();
        } else {
            cp_wait<0>();
        }
        __syncthreads();
        const int buf = c & 1;
#pragma unroll
        for (int ks = 0; ks < 4; ks++) {
            uint32_t af[4][4], bq[4][2];
#pragma unroll
            for (int i = 0; i < 4; i++)
                ldsm4(af[i], smem_u32(&As[buf * 256 + m0 + i * 16 + (lane & 15)][ks * 16 + ((lane >> 4) << 3)]));
#pragma unroll
            for (int j = 0; j < 4; j++)
                ldsm2t(bq[j], smem_u32(&Bs[buf * 64 + ks * 16 + (lane & 15)][n0 + j * 8]));
#pragma unroll
            for (int i = 0; i < 4; i++)
#pragma unroll
                for (int j = 0; j < 4; j++) mma_bf16(acc[i][j], af[i], bq[j]);
        }
        if (more) {
            int nb = (c + 1) & 1;
            *(uint4*)&Bs[nb * 64 + brow][bcol] = make_uint4(pk2(pb[0].x, pb[0].y), pk2(pb[0].z, pb[0].w),
                                                            pk2(pb[1].x, pb[1].y), pk2(pb[1].z, pb[1].w));
            *(uint4*)&Bs[nb * 64 + brow][bcol + 8] = make_uint4(pk2(pb[2].x, pb[2].y), pk2(pb[2].z, pb[2].w),
                                                                pk2(pb[3].x, pb[3].y), pk2(pb[3].z, pb[3].w));
        }
    }

    const int r = lane >> 2, cpr = (lane & 3) * 2;
#pragma unroll
    for (int i = 0; i < 4; i++) {
        int c_ = m0 + i * 16 + r;
        float b0 = g_bias[c_], b1 = g_bias[c_ + 8];
        const float* x0 = X + ((size_t)(n * C_DIM + c_)) * L_DIM + l0;
        const float* x1 = x0 + (size_t)8 * L_DIM;
        float* o0 = out + ((size_t)(n * C_DIM + c_)) * L_DIM + l0;
        float* o1 = o0 + (size_t)8 * L_DIM;
#pragma unroll
        for (int j = 0; j < 4; j++) {
            int l = n0 + j * 8 + cpr;
            float2 xv0 = *(const float2*)(x0 + l);
            float2 xv1 = *(const float2*)(x1 + l);
            float2 ov0 = make_float2(acc[i][j][0] + xv0.x - b0, acc[i][j][1] + xv0.y - b0);
            float2 ov1 = make_float2(acc[i][j][2] + xv1.x - b1, acc[i][j][3] + xv1.y - b1);
            *(float2*)(o0 + l) = ov0;
            *(float2*)(o1 + l) = ov1;
        }
    }
}

// ---------------- launch ----------------
extern "C" void kernel_launch(void* const* d_in, const int* in_sizes, int n_in,
                              void* d_out, int out_size) {
    const float* X = (const float*)d_in[0];
    float* out = (float*)d_out;

    cudaFuncSetAttribute(apply_kernel, cudaFuncAttributeMaxDynamicSharedMemorySize, APPLY_SMEM);

    zero_kernel<<<256, 256>>>();
    gramL_kernel<<<dim3(N_DIM, 4), 512>>>(X);
    gramD_kernel<<<dim3(N_DIM, 4), 256>>>(X);
    buildA_kernel<<<48, 256>>>();
    pgemmA2_kernel<<<dim3(4, 4, 4), 256>>>();
    final_gemm_kernel<<<dim3(4, 4), 256>>>();
    apply_kernel<<<dim3(32, N_DIM), 512, APPLY_SMEM>>>(X, out);
}

// round 14
// speedup vs baseline: 1.0390x; 1.0390x over previous
#include <cuda_runtime.h>
#include <cuda_bf16.h>
#include <cstdint>
#include <cstddef>

#define C_DIM 256
#define L_DIM 4096
#define N_DIM 64
#define M_TOT (N_DIM * L_DIM)   // 262144
#define EPSV 1e-3f

// ---------------- scratch (device globals) ----------------
__device__ __nv_bfloat16 g_Wb[C_DIM * C_DIM];   // bf16 (wm - I)
__device__ float g_mean[C_DIM];                 // raw channel sums
__device__ float g_gram[C_DIM * C_DIM];         // raw X X^T sums (Q00, Q10, Q11 used)
__device__ float g_A[C_DIM * C_DIM];
__device__ float g_A2[C_DIM * C_DIM];           // atomic accum: A@A
__device__ float g_bias[C_DIM];
__device__ float g_scal[1];                     // rsqrt(s)

// ---------------- low-level helpers ----------------
__device__ __forceinline__ uint32_t smem_u32(const void* p) {
    return (uint32_t)__cvta_generic_to_shared(p);
}
__device__ __forceinline__ void cp16(uint32_t saddr, const void* g) {
    asm volatile("cp.async.cg.shared.global [%0], [%1], 16;\n" :: "r"(saddr), "l"(g));
}
__device__ __forceinline__ void cp_commit() { asm volatile("cp.async.commit_group;\n"); }
template<int N> __device__ __forceinline__ void cp_wait() {
    asm volatile("cp.async.wait_group %0;\n" :: "n"(N));
}
__device__ __forceinline__ void ldsm4(uint32_t r[4], uint32_t a) {
    asm volatile("ldmatrix.sync.aligned.m8n8.x4.shared.b16 {%0,%1,%2,%3}, [%4];"
                 : "=r"(r[0]), "=r"(r[1]), "=r"(r[2]), "=r"(r[3]) : "r"(a));
}
__device__ __forceinline__ void ldsm2(uint32_t r[2], uint32_t a) {
    asm volatile("ldmatrix.sync.aligned.m8n8.x2.shared.b16 {%0,%1}, [%2];"
                 : "=r"(r[0]), "=r"(r[1]) : "r"(a));
}
__device__ __forceinline__ void ldsm2t(uint32_t r[2], uint32_t a) {
    asm volatile("ldmatrix.sync.aligned.m8n8.x2.trans.shared.b16 {%0,%1}, [%2];"
                 : "=r"(r[0]), "=r"(r[1]) : "r"(a));
}
__device__ __forceinline__ void mma_bf16(float d[4], const uint32_t a[4], const uint32_t b[2]) {
    asm volatile("mma.sync.aligned.m16n8k16.row.col.f32.bf16.bf16.f32 "
                 "{%0,%1,%2,%3}, {%4,%5,%6,%7}, {%8,%9}, {%0,%1,%2,%3};"
                 : "+f"(d[0]), "+f"(d[1]), "+f"(d[2]), "+f"(d[3])
                 : "r"(a[0]), "r"(a[1]), "r"(a[2]), "r"(a[3]), "r"(b[0]), "r"(b[1]));
}
__device__ __forceinline__ uint32_t pk2(float x, float y) {
    __nv_bfloat162 h = __floats2bfloat162_rn(x, y);
    return *(uint32_t*)&h;
}

// ---------------- zero accumulators (vectorized) ----------------
__global__ void zero_kernel() {
    int idx = blockIdx.x * 256 + threadIdx.x;    // 64 blocks -> 16384 threads
    float4 z = make_float4(0.f, 0.f, 0.f, 0.f);
    *(float4*)&g_gram[idx * 4] = z;
    *(float4*)&g_A2[idx * 4] = z;
    if (idx < C_DIM) { g_mean[idx] = 0.f; g_bias[idx] = 0.f; }
}

// ---------------- gramL: left half (rows 0..255) x (cols 0..127), ONE shared tile ----------------
__global__ __launch_bounds__(512, 1) void gramL_kernel(const float* __restrict__ X) {
    __shared__ __align__(16) __nv_bfloat16 Ts[2][256][40];
    const int n = blockIdx.x, zh = blockIdx.y;
    const int tid = threadIdx.x, wid = tid >> 5, lane = tid & 31;
    const int m0 = (wid >> 2) * 64, n0 = (wid & 3) * 32;
    const int row = tid >> 1, seg = (tid & 1) * 16;

    const float* Ag = X + ((size_t)(n * C_DIM + row)) * L_DIM + zh * 1024 + seg;

    float acc[4][4][4];
#pragma unroll
    for (int i = 0; i < 4; i++)
#pragma unroll
        for (int j = 0; j < 4; j++)
#pragma unroll
            for (int r = 0; r < 4; r++) acc[i][j][r] = 0.f;
    float msum = 0.f;
    float4 pa[4];

#pragma unroll
    for (int q = 0; q < 4; q++) pa[q] = *(const float4*)(Ag + q * 4);
    msum += (pa[0].x + pa[0].y + pa[0].z + pa[0].w) + (pa[1].x + pa[1].y + pa[1].z + pa[1].w)
          + (pa[2].x + pa[2].y + pa[2].z + pa[2].w) + (pa[3].x + pa[3].y + pa[3].z + pa[3].w);
    *(uint4*)&Ts[0][row][seg] = make_uint4(pk2(pa[0].x, pa[0].y), pk2(pa[0].z, pa[0].w),
                                           pk2(pa[1].x, pa[1].y), pk2(pa[1].z, pa[1].w));
    *(uint4*)&Ts[0][row][seg + 8] = make_uint4(pk2(pa[2].x, pa[2].y), pk2(pa[2].z, pa[2].w),
                                               pk2(pa[3].x, pa[3].y), pk2(pa[3].z, pa[3].w));

#pragma unroll 1
    for (int c = 0; c < 32; c++) {
        __syncthreads();
        const bool more = (c + 1 < 32);
        if (more) {
#pragma unroll
            for (int q = 0; q < 4; q++) pa[q] = *(const float4*)(Ag + (c + 1) * 32 + q * 4);
        }
        const int buf = c & 1;
#pragma unroll
        for (int ks = 0; ks < 2; ks++) {
            uint32_t af[4][4], bq[4][2];
#pragma unroll
            for (int i = 0; i < 4; i++)
                ldsm4(af[i], smem_u32(&Ts[buf][m0 + i * 16 + (lane & 15)][ks * 16 + ((lane >> 4) << 3)]));
#pragma unroll
            for (int j = 0; j < 4; j++)
                ldsm2(bq[j], smem_u32(&Ts[buf][n0 + j * 8 + (lane & 7)][ks * 16 + (lane & 8)]));
#pragma unroll
            for (int i = 0; i < 4; i++)
#pragma unroll
                for (int j = 0; j < 4; j++) mma_bf16(acc[i][j], af[i], bq[j]);
        }
        if (more) {
            const int nb = (c + 1) & 1;
            msum += (pa[0].x + pa[0].y + pa[0].z + pa[0].w) + (pa[1].x + pa[1].y + pa[1].z + pa[1].w)
                  + (pa[2].x + pa[2].y + pa[2].z + pa[2].w) + (pa[3].x + pa[3].y + pa[3].z + pa[3].w);
            *(uint4*)&Ts[nb][row][seg] = make_uint4(pk2(pa[0].x, pa[0].y), pk2(pa[0].z, pa[0].w),
                                                    pk2(pa[1].x, pa[1].y), pk2(pa[1].z, pa[1].w));
            *(uint4*)&Ts[nb][row][seg + 8] = make_uint4(pk2(pa[2].x, pa[2].y), pk2(pa[2].z, pa[2].w),
                                                        pk2(pa[3].x, pa[3].y), pk2(pa[3].z, pa[3].w));
        }
    }

    atomicAdd(&g_mean[row], msum);

    const int r = lane >> 2, cpr = (lane & 3) * 2;
#pragma unroll
    for (int i = 0; i < 4; i++)
#pragma unroll
        for (int j = 0; j < 4; j++) {
            int gi = m0 + i * 16 + r;
            int gj = n0 + j * 8 + cpr;
            atomicAdd(&g_gram[gi * C_DIM + gj], acc[i][j][0]);
            atomicAdd(&g_gram[gi * C_DIM + gj + 1], acc[i][j][1]);
            atomicAdd(&g_gram[(gi + 8) * C_DIM + gj], acc[i][j][2]);
            atomicAdd(&g_gram[(gi + 8) * C_DIM + gj + 1], acc[i][j][3]);
        }
}

// ---------------- gramD: Q11 diagonal block (rows/cols 128..255), A=B one tile ----------------
__global__ __launch_bounds__(256, 2) void gramD_kernel(const float* __restrict__ X) {
    __shared__ __align__(16) __nv_bfloat16 Ts[2][128][40];
    const int n = blockIdx.x, zh = blockIdx.y;
    const int tid = threadIdx.x, wid = tid >> 5, lane = tid & 31;
    const int m0 = (wid >> 2) * 64, n0 = (wid & 3) * 32;
    const int row = tid >> 1, seg = (tid & 1) * 16;

    const float* Ag = X + ((size_t)(n * C_DIM + 128 + row)) * L_DIM + zh * 1024 + seg;

    float acc[4][4][4];
#pragma unroll
    for (int i = 0; i < 4; i++)
#pragma unroll
        for (int j = 0; j < 4; j++)
#pragma unroll
            for (int r = 0; r < 4; r++) acc[i][j][r] = 0.f;
    float4 pa[4];

#pragma unroll
    for (int q = 0; q < 4; q++) pa[q] = *(const float4*)(Ag + q * 4);
    *(uint4*)&Ts[0][row][seg] = make_uint4(pk2(pa[0].x, pa[0].y), pk2(pa[0].z, pa[0].w),
                                           pk2(pa[1].x, pa[1].y), pk2(pa[1].z, pa[1].w));
    *(uint4*)&Ts[0][row][seg + 8] = make_uint4(pk2(pa[2].x, pa[2].y), pk2(pa[2].z, pa[2].w),
                                               pk2(pa[3].x, pa[3].y), pk2(pa[3].z, pa[3].w));

#pragma unroll 1
    for (int c = 0; c < 32; c++) {
        __syncthreads();
        const bool more = (c + 1 < 32);
        if (more) {
#pragma unroll
            for (int q = 0; q < 4; q++) pa[q] = *(const float4*)(Ag + (c + 1) * 32 + q * 4);
        }
        const int buf = c & 1;
#pragma unroll
        for (int ks = 0; ks < 2; ks++) {
            uint32_t af[4][4], bq[4][2];
#pragma unroll
            for (int i = 0; i < 4; i++)
                ldsm4(af[i], smem_u32(&Ts[buf][m0 + i * 16 + (lane & 15)][ks * 16 + ((lane >> 4) << 3)]));
#pragma unroll
            for (int j = 0; j < 4; j++)
                ldsm2(bq[j], smem_u32(&Ts[buf][n0 + j * 8 + (lane & 7)][ks * 16 + (lane & 8)]));
#pragma unroll
            for (int i = 0; i < 4; i++)
#pragma unroll
                for (int j = 0; j < 4; j++) mma_bf16(acc[i][j], af[i], bq[j]);
        }
        if (more) {
            const int nb = (c + 1) & 1;
            *(uint4*)&Ts[nb][row][seg] = make_uint4(pk2(pa[0].x, pa[0].y), pk2(pa[0].z, pa[0].w),
                                                    pk2(pa[1].x, pa[1].y), pk2(pa[1].z, pa[1].w));
            *(uint4*)&Ts[nb][row][seg + 8] = make_uint4(pk2(pa[2].x, pa[2].y), pk2(pa[2].z, pa[2].w),
                                                        pk2(pa[3].x, pa[3].y), pk2(pa[3].z, pa[3].w));
        }
    }

    const int r = lane >> 2, cpr = (lane & 3) * 2;
#pragma unroll
    for (int i = 0; i < 4; i++)
#pragma unroll
        for (int j = 0; j < 4; j++) {
            int gi = 128 + m0 + i * 16 + r;
            int gj = 128 + n0 + j * 8 + cpr;
            atomicAdd(&g_gram[gi * C_DIM + gj], acc[i][j][0]);
            atomicAdd(&g_gram[gi * C_DIM + gj + 1], acc[i][j][1]);
            atomicAdd(&g_gram[(gi + 8) * C_DIM + gj], acc[i][j][2]);
            atomicAdd(&g_gram[(gi + 8) * C_DIM + gj + 1], acc[i][j][3]);
        }
}

// ---------------- buildA (fused trace): quadrants Q00, Q10 (mirror->Q01), Q11 ----------------
__global__ void buildA_kernel() {
    __shared__ float red[256];
    const float invm = 1.f / (float)M_TOT;
    int t = threadIdx.x;
    {
        float mu = g_mean[t] * invm;
        red[t] = g_gram[t * (C_DIM + 1)] * invm - mu * mu + EPSV;
    }
    __syncthreads();
    for (int s = 128; s > 0; s >>= 1) {
        if (t < s) red[t] += red[t + s];
        __syncthreads();
    }
    float sv = red[0] / (float)C_DIM;
    float invs = 1.f / sv;
    if (blockIdx.x == 0 && t == 0) g_scal[0] = rsqrtf(sv);

    int base = blockIdx.x * 1024 + t * 4;
#pragma unroll
    for (int u = 0; u < 4; u++) {
        int idx = base + u;
        int q = idx >> 14, rr = idx & 16383;
        int i, j;
        if (q == 0)      { i = rr >> 7;         j = rr & 127; }
        else if (q == 1) { i = 128 + (rr >> 7); j = rr & 127; }
        else             { i = 128 + (rr >> 7); j = 128 + (rr & 127); }
        float sig = g_gram[i * C_DIM + j] * invm - (g_mean[i] * invm) * (g_mean[j] * invm);
        if (i == j) sig += EPSV;
        float v = sig * invs - ((i == j) ? 1.f : 0.f);
        g_A[i * C_DIM + j] = v;
        if (q == 1) g_A[j * C_DIM + i] = v;
    }
}

// ---------------- small fp32 64x64-tile GEMM core, K range [kb, ke) ----------------
__device__ __forceinline__ void small_gemm64(const float* __restrict__ A, const float* __restrict__ B,
                                             float acc[4][4], int i0, int j0, int kb, int ke) {
    __shared__ float As[16][68];
    __shared__ float Bs[16][68];
    const int tid = threadIdx.x;
    const int tx = tid & 15, ty = tid >> 4;
    const int arow = tid >> 2, akq = (tid & 3) * 4;
    for (int k0 = kb; k0 < ke; k0 += 16) {
        __syncthreads();
        float4 va = *(const float4*)&A[(i0 + arow) * C_DIM + k0 + akq];
        As[akq + 0][arow] = va.x; As[akq + 1][arow] = va.y;
        As[akq + 2][arow] = va.z; As[akq + 3][arow] = va.w;
        float4 vb = *(const float4*)&B[(k0 + ty) * C_DIM + j0 + tx * 4];
        *(float4*)&Bs[ty][tx * 4] = vb;
        __syncthreads();
#pragma unroll
        for (int k = 0; k < 16; k++) {
            float4 a = *(const float4*)&As[k][ty * 4];
            float4 b = *(const float4*)&Bs[k][tx * 4];
            float av[4] = {a.x, a.y, a.z, a.w};
            float bv[4] = {b.x, b.y, b.z, b.w};
#pragma unroll
            for (int r = 0; r < 4; r++)
#pragma unroll
                for (int c = 0; c < 4; c++) acc[r][c] = fmaf(av[r], bv[c], acc[r][c]);
        }
    }
}

// ---------------- A2 = A@A, split-K x4, atomic accumulate ----------------
__global__ void pgemmA2_kernel() {
    int i0 = blockIdx.y * 64, j0 = blockIdx.x * 64, z = blockIdx.z;
    float acc[4][4] = {};
    small_gemm64(g_A, g_A, acc, i0, j0, z * 64, z * 64 + 64);
    int tx = threadIdx.x & 15, ty = threadIdx.x >> 4;
#pragma unroll
    for (int r = 0; r < 4; r++)
#pragma unroll
        for (int c = 0; c < 4; c++)
            atomicAdd(&g_A2[(i0 + ty * 4 + r) * C_DIM + j0 + tx * 4 + c], acc[r][c]);
}

// ---------------- final: acc = Q@A2 with Q built in the A-tile load ----------------
__global__ void final_gemm_kernel() {
    const float c1 = -0.5f, c2 = 0.375f, c3 = -0.3125f, c4 = 0.2734375f;
    __shared__ float As[16][68];
    __shared__ float Bs[16][68];
    int i0 = blockIdx.y * 64, j0 = blockIdx.x * 64;
    const int tid = threadIdx.x;
    const int tx = tid & 15, ty = tid >> 4;
    const int arow = tid >> 2, akq = (tid & 3) * 4;
    float acc[4][4] = {};

    for (int k0 = 0; k0 < C_DIM; k0 += 16) {
        __syncthreads();
        int gi = i0 + arow, gk = k0 + akq;
        float4 a1 = *(const float4*)&g_A[gi * C_DIM + gk];
        float4 a2 = *(const float4*)&g_A2[gi * C_DIM + gk];
        As[akq + 0][arow] = c3 * a1.x + c4 * a2.x + ((gi == gk + 0) ? c2 : 0.f);
        As[akq + 1][arow] = c3 * a1.y + c4 * a2.y + ((gi == gk + 1) ? c2 : 0.f);
        As[akq + 2][arow] = c3 * a1.z + c4 * a2.z + ((gi == gk + 2) ? c2 : 0.f);
        As[akq + 3][arow] = c3 * a1.w + c4 * a2.w + ((gi == gk + 3) ? c2 : 0.f);
        float4 vb = *(const float4*)&g_A2[(k0 + ty) * C_DIM + j0 + tx * 4];
        *(float4*)&Bs[ty][tx * 4] = vb;
        __syncthreads();
#pragma unroll
        for (int k = 0; k < 16; k++) {
            float4 a = *(const float4*)&As[k][ty * 4];
            float4 b = *(const float4*)&Bs[k][tx * 4];
            float av[4] = {a.x, a.y, a.z, a.w};
            float bv[4] = {b.x, b.y, b.z, b.w};
#pragma unroll
            for (int r = 0; r < 4; r++)
#pragma unroll
                for (int c = 0; c < 4; c++) acc[r][c] = fmaf(av[r], bv[c], acc[r][c]);
        }
    }

    float rs = g_scal[0];
    const float invm = 1.f / (float)M_TOT;
#pragma unroll
    for (int r = 0; r < 4; r++) {
        int gi = i0 + ty * 4 + r;
        float bsum = 0.f;
#pragma unroll
        for (int c = 0; c < 4; c++) {
            int gj = j0 + tx * 4 + c;
            float d = (gi == gj) ? 1.f : 0.f;
            float w = rs * (d + c1 * g_A[gi * C_DIM + gj] + acc[r][c]);
            g_Wb[gi * C_DIM + gj] = __float2bfloat16(w - d);
            bsum += w * (g_mean[gj] * invm);
        }
        atomicAdd(&g_bias[gi], bsum);
    }
}

// ---------------- apply: out = (wm-I)@bf16(X) + X - bias ; M=256 tile (R12 form verbatim) ----------------
#define APPLY_SMEM (2 * 256 * 40 * 2 + 2 * 32 * 136 * 2)   // 58368 bytes
__global__ __launch_bounds__(512, 1) void apply_kernel(const float* __restrict__ X,
                                                       float* __restrict__ out) {
    extern __shared__ __align__(16) char sm[];
    __nv_bfloat16 (*As)[40] = (__nv_bfloat16 (*)[40])sm;
    __nv_bfloat16 (*Bs)[136] = (__nv_bfloat16 (*)[136])(sm + 2 * 256 * 40 * 2);
    const int l0 = blockIdx.x * 128, n = blockIdx.y;
    const int tid = threadIdx.x, wid = tid >> 5, lane = tid & 31;
    const int m0 = (wid >> 2) * 64, n0 = (wid & 3) * 32;
    const int arow = tid >> 1, aseg = (tid & 1) * 16;
    const int brow = tid >> 4, bcol = (tid & 15) * 8;

    const __nv_bfloat16* Ag = g_Wb + arow * C_DIM + aseg;
    const float* Bg = X + ((size_t)(n * C_DIM + brow)) * L_DIM + l0 + bcol;

    float acc[4][4][4];
#pragma unroll
    for (int i = 0; i < 4; i++)
#pragma unroll
        for (int j = 0; j < 4; j++)
#pragma unroll
            for (int r = 0; r < 4; r++) acc[i][j][r] = 0.f;

    uint32_t sA0 = smem_u32(&As[arow][aseg]);
    const uint32_t aStride = 256 * 40 * 2;
    float4 pb0, pb1;

    cp16(sA0, Ag);
    cp16(sA0 + 16, Ag + 8);
    pb0 = *(const float4*)(Bg);
    pb1 = *(const float4*)(Bg + 4);
    cp_commit();
    *(uint4*)&Bs[brow][bcol] = make_uint4(pk2(pb0.x, pb0.y), pk2(pb0.z, pb0.w),
                                          pk2(pb1.x, pb1.y), pk2(pb1.z, pb1.w));

#pragma unroll 1
    for (int c = 0; c < 8; c++) {
        const bool more = (c + 1 < 8);
        if (more) {
            int k0n = (c + 1) * 32;
            int nb = (c + 1) & 1;
            cp16(sA0 + nb * aStride, Ag + k0n);
            cp16(sA0 + nb * aStride + 16, Ag + k0n + 8);
            pb0 = *(const float4*)(Bg + (size_t)k0n * L_DIM);
            pb1 = *(const float4*)(Bg + (size_t)k0n * L_DIM + 4);
            cp_commit();
            cp_wait<1>();
        } else {
            cp_wait<0>();
        }
        __syncthreads();
        const int buf = c & 1;
#pragma unroll
        for (int ks = 0; ks < 2; ks++) {
            uint32_t af[4][4], bq[4][2];
#pragma unroll
            for (int i = 0; i < 4; i++)
                ldsm4(af[i], smem_u32(&As[buf * 256 + m0 + i * 16 + (lane & 15)][ks * 16 + ((lane >> 4) << 3)]));
#pragma unroll
            for (int j = 0; j < 4; j++)
                ldsm2t(bq[j], smem_u32(&Bs[buf * 32 + ks * 16 + (lane & 15)][n0 + j * 8]));
#pragma unroll
            for (int i = 0; i < 4; i++)
#pragma unroll
                for (int j = 0; j < 4; j++) mma_bf16(acc[i][j], af[i], bq[j]);
        }
        if (more) {
            int nb = (c + 1) & 1;
            *(uint4*)&Bs[nb * 32 + brow][bcol] = make_uint4(pk2(pb0.x, pb0.y), pk2(pb0.z, pb0.w),
                                                            pk2(pb1.x, pb1.y), pk2(pb1.z, pb1.w));
        }
    }

    const int r = lane >> 2, cpr = (lane & 3) * 2;
#pragma unroll
    for (int i = 0; i < 4; i++) {
        int c_ = m0 + i * 16 + r;
        float b0 = g_bias[c_], b1 = g_bias[c_ + 8];
        const float* x0 = X + ((size_t)(n * C_DIM + c_)) * L_DIM + l0;
        const float* x1 = x0 + (size_t)8 * L_DIM;
        float* o0 = out + ((size_t)(n * C_DIM + c_)) * L_DIM + l0;
        float* o1 = o0 + (size_t)8 * L_DIM;
#pragma unroll
        for (int j = 0; j < 4; j++) {
            int l = n0 + j * 8 + cpr;
            float2 xv0 = *(const float2*)(x0 + l);
            float2 xv1 = *(const float2*)(x1 + l);
            float2 ov0 = make_float2(acc[i][j][0] + xv0.x - b0, acc[i][j][1] + xv0.y - b0);
            float2 ov1 = make_float2(acc[i][j][2] + xv1.x - b1, acc[i][j][3] + xv1.y - b1);
            *(float2*)(o0 + l) = ov0;
            *(float2*)(o1 + l) = ov1;
        }
    }
}

// ---------------- launch ----------------
extern "C" void kernel_launch(void* const* d_in, const int* in_sizes, int n_in,
                              void* d_out, int out_size) {
    const float* X = (const float*)d_in[0];
    float* out = (float*)d_out;

    cudaFuncSetAttribute(apply_kernel, cudaFuncAttributeMaxDynamicSharedMemorySize, APPLY_SMEM);

    zero_kernel<<<64, 256>>>();
    gramL_kernel<<<dim3(N_DIM, 4), 512>>>(X);
    gramD_kernel<<<dim3(N_DIM, 4), 256>>>(X);
    buildA_kernel<<<48, 256>>>();
    pgemmA2_kernel<<<dim3(4, 4, 4), 256>>>();
    final_gemm_kernel<<<dim3(4, 4), 256>>>();
    apply_kernel<<<dim3(32, N_DIM), 512, APPLY_SMEM>>>(X, out);
}

// round 15
// speedup vs baseline: 1.0625x; 1.0226x over previous
#include <cuda_runtime.h>
#include <cuda_bf16.h>
#include <cstdint>
#include <cstddef>

#define C_DIM 256
#define L_DIM 4096
#define N_DIM 64
#define M_TOT (N_DIM * L_DIM)   // 262144
#define EPSV 1e-3f

// ---------------- scratch (device globals) ----------------
__device__ __nv_bfloat16 g_Wb[C_DIM * C_DIM];   // bf16 (wm - I)
__device__ float g_mean[C_DIM];                 // raw channel sums
__device__ float g_gram[C_DIM * C_DIM];         // raw X X^T sums (Q00, Q10, Q11 used)
__device__ float g_A[C_DIM * C_DIM];
__device__ float g_A2[C_DIM * C_DIM];           // atomic accum: A@A
__device__ float g_bias[C_DIM];
__device__ float g_scal[1];                     // rsqrt(s)

// ---------------- low-level helpers ----------------
__device__ __forceinline__ uint32_t smem_u32(const void* p) {
    return (uint32_t)__cvta_generic_to_shared(p);
}
__device__ __forceinline__ void cp16(uint32_t saddr, const void* g) {
    asm volatile("cp.async.cg.shared.global [%0], [%1], 16;\n" :: "r"(saddr), "l"(g));
}
__device__ __forceinline__ void cp_commit() { asm volatile("cp.async.commit_group;\n"); }
template<int N> __device__ __forceinline__ void cp_wait() {
    asm volatile("cp.async.wait_group %0;\n" :: "n"(N));
}
__device__ __forceinline__ void ldsm4(uint32_t r[4], uint32_t a) {
    asm volatile("ldmatrix.sync.aligned.m8n8.x4.shared.b16 {%0,%1,%2,%3}, [%4];"
                 : "=r"(r[0]), "=r"(r[1]), "=r"(r[2]), "=r"(r[3]) : "r"(a));
}
__device__ __forceinline__ void ldsm2(uint32_t r[2], uint32_t a) {
    asm volatile("ldmatrix.sync.aligned.m8n8.x2.shared.b16 {%0,%1}, [%2];"
                 : "=r"(r[0]), "=r"(r[1]) : "r"(a));
}
__device__ __forceinline__ void ldsm2t(uint32_t r[2], uint32_t a) {
    asm volatile("ldmatrix.sync.aligned.m8n8.x2.trans.shared.b16 {%0,%1}, [%2];"
                 : "=r"(r[0]), "=r"(r[1]) : "r"(a));
}
__device__ __forceinline__ void mma_bf16(float d[4], const uint32_t a[4], const uint32_t b[2]) {
    asm volatile("mma.sync.aligned.m16n8k16.row.col.f32.bf16.bf16.f32 "
                 "{%0,%1,%2,%3}, {%4,%5,%6,%7}, {%8,%9}, {%0,%1,%2,%3};"
                 : "+f"(d[0]), "+f"(d[1]), "+f"(d[2]), "+f"(d[3])
                 : "r"(a[0]), "r"(a[1]), "r"(a[2]), "r"(a[3]), "r"(b[0]), "r"(b[1]));
}
__device__ __forceinline__ uint32_t pk2(float x, float y) {
    __nv_bfloat162 h = __floats2bfloat162_rn(x, y);
    return *(uint32_t*)&h;
}

// ---------------- zero accumulators (vectorized) ----------------
__global__ void zero_kernel() {
    int idx = blockIdx.x * 256 + threadIdx.x;    // 64 blocks -> 16384 threads
    float4 z = make_float4(0.f, 0.f, 0.f, 0.f);
    *(float4*)&g_gram[idx * 4] = z;
    *(float4*)&g_A2[idx * 4] = z;
    if (idx < C_DIM) { g_mean[idx] = 0.f; g_bias[idx] = 0.f; }
}

// ---------------- gramL: left half (rows 0..255) x (cols 0..127), ONE shared tile ----------------
__global__ __launch_bounds__(512, 1) void gramL_kernel(const float* __restrict__ X) {
    // PDL: allow the dependent gramD launch as soon as every gramL CTA has started.
    cudaTriggerProgrammaticLaunchCompletion();

    __shared__ __align__(16) __nv_bfloat16 Ts[2][256][40];
    const int n = blockIdx.x, zh = blockIdx.y;
    const int tid = threadIdx.x, wid = tid >> 5, lane = tid & 31;
    const int m0 = (wid >> 2) * 64, n0 = (wid & 3) * 32;
    const int row = tid >> 1, seg = (tid & 1) * 16;

    const float* Ag = X + ((size_t)(n * C_DIM + row)) * L_DIM + zh * 1024 + seg;

    float acc[4][4][4];
#pragma unroll
    for (int i = 0; i < 4; i++)
#pragma unroll
        for (int j = 0; j < 4; j++)
#pragma unroll
            for (int r = 0; r < 4; r++) acc[i][j][r] = 0.f;
    float msum = 0.f;
    float4 pa[4];

#pragma unroll
    for (int q = 0; q < 4; q++) pa[q] = *(const float4*)(Ag + q * 4);
    msum += (pa[0].x + pa[0].y + pa[0].z + pa[0].w) + (pa[1].x + pa[1].y + pa[1].z + pa[1].w)
          + (pa[2].x + pa[2].y + pa[2].z + pa[2].w) + (pa[3].x + pa[3].y + pa[3].z + pa[3].w);
    *(uint4*)&Ts[0][row][seg] = make_uint4(pk2(pa[0].x, pa[0].y), pk2(pa[0].z, pa[0].w),
                                           pk2(pa[1].x, pa[1].y), pk2(pa[1].z, pa[1].w));
    *(uint4*)&Ts[0][row][seg + 8] = make_uint4(pk2(pa[2].x, pa[2].y), pk2(pa[2].z, pa[2].w),
                                               pk2(pa[3].x, pa[3].y), pk2(pa[3].z, pa[3].w));

#pragma unroll 1
    for (int c = 0; c < 32; c++) {
        __syncthreads();
        const bool more = (c + 1 < 32);
        if (more) {
#pragma unroll
            for (int q = 0; q < 4; q++) pa[q] = *(const float4*)(Ag + (c + 1) * 32 + q * 4);
        }
        const int buf = c & 1;
#pragma unroll
        for (int ks = 0; ks < 2; ks++) {
            uint32_t af[4][4], bq[4][2];
#pragma unroll
            for (int i = 0; i < 4; i++)
                ldsm4(af[i], smem_u32(&Ts[buf][m0 + i * 16 + (lane & 15)][ks * 16 + ((lane >> 4) << 3)]));
#pragma unroll
            for (int j = 0; j < 4; j++)
                ldsm2(bq[j], smem_u32(&Ts[buf][n0 + j * 8 + (lane & 7)][ks * 16 + (lane & 8)]));
#pragma unroll
            for (int i = 0; i < 4; i++)
#pragma unroll
                for (int j = 0; j < 4; j++) mma_bf16(acc[i][j], af[i], bq[j]);
        }
        if (more) {
            const int nb = (c + 1) & 1;
            msum += (pa[0].x + pa[0].y + pa[0].z + pa[0].w) + (pa[1].x + pa[1].y + pa[1].z + pa[1].w)
                  + (pa[2].x + pa[2].y + pa[2].z + pa[2].w) + (pa[3].x + pa[3].y + pa[3].z + pa[3].w);
            *(uint4*)&Ts[nb][row][seg] = make_uint4(pk2(pa[0].x, pa[0].y), pk2(pa[0].z, pa[0].w),
                                                    pk2(pa[1].x, pa[1].y), pk2(pa[1].z, pa[1].w));
            *(uint4*)&Ts[nb][row][seg + 8] = make_uint4(pk2(pa[2].x, pa[2].y), pk2(pa[2].z, pa[2].w),
                                                        pk2(pa[3].x, pa[3].y), pk2(pa[3].z, pa[3].w));
        }
    }

    atomicAdd(&g_mean[row], msum);

    const int r = lane >> 2, cpr = (lane & 3) * 2;
#pragma unroll
    for (int i = 0; i < 4; i++)
#pragma unroll
        for (int j = 0; j < 4; j++) {
            int gi = m0 + i * 16 + r;
            int gj = n0 + j * 8 + cpr;
            atomicAdd(&g_gram[gi * C_DIM + gj], acc[i][j][0]);
            atomicAdd(&g_gram[gi * C_DIM + gj + 1], acc[i][j][1]);
            atomicAdd(&g_gram[(gi + 8) * C_DIM + gj], acc[i][j][2]);
            atomicAdd(&g_gram[(gi + 8) * C_DIM + gj + 1], acc[i][j][3]);
        }
}

// ---------------- gramD: Q11 diagonal block (rows/cols 128..255), A=B one tile ----------------
__global__ __launch_bounds__(256, 2) void gramD_kernel(const float* __restrict__ X) {
    __shared__ __align__(16) __nv_bfloat16 Ts[2][128][40];
    const int n = blockIdx.x, zh = blockIdx.y;
    const int tid = threadIdx.x, wid = tid >> 5, lane = tid & 31;
    const int m0 = (wid >> 2) * 64, n0 = (wid & 3) * 32;
    const int row = tid >> 1, seg = (tid & 1) * 16;

    const float* Ag = X + ((size_t)(n * C_DIM + 128 + row)) * L_DIM + zh * 1024 + seg;

    float acc[4][4][4];
#pragma unroll
    for (int i = 0; i < 4; i++)
#pragma unroll
        for (int j = 0; j < 4; j++)
#pragma unroll
            for (int r = 0; r < 4; r++) acc[i][j][r] = 0.f;
    float4 pa[4];

#pragma unroll
    for (int q = 0; q < 4; q++) pa[q] = *(const float4*)(Ag + q * 4);
    *(uint4*)&Ts[0][row][seg] = make_uint4(pk2(pa[0].x, pa[0].y), pk2(pa[0].z, pa[0].w),
                                           pk2(pa[1].x, pa[1].y), pk2(pa[1].z, pa[1].w));
    *(uint4*)&Ts[0][row][seg + 8] = make_uint4(pk2(pa[2].x, pa[2].y), pk2(pa[2].z, pa[2].w),
                                               pk2(pa[3].x, pa[3].y), pk2(pa[3].z, pa[3].w));

#pragma unroll 1
    for (int c = 0; c < 32; c++) {
        __syncthreads();
        const bool more = (c + 1 < 32);
        if (more) {
#pragma unroll
            for (int q = 0; q < 4; q++) pa[q] = *(const float4*)(Ag + (c + 1) * 32 + q * 4);
        }
        const int buf = c & 1;
#pragma unroll
        for (int ks = 0; ks < 2; ks++) {
            uint32_t af[4][4], bq[4][2];
#pragma unroll
            for (int i = 0; i < 4; i++)
                ldsm4(af[i], smem_u32(&Ts[buf][m0 + i * 16 + (lane & 15)][ks * 16 + ((lane >> 4) << 3)]));
#pragma unroll
            for (int j = 0; j < 4; j++)
                ldsm2(bq[j], smem_u32(&Ts[buf][n0 + j * 8 + (lane & 7)][ks * 16 + (lane & 8)]));
#pragma unroll
            for (int i = 0; i < 4; i++)
#pragma unroll
                for (int j = 0; j < 4; j++) mma_bf16(acc[i][j], af[i], bq[j]);
        }
        if (more) {
            const int nb = (c + 1) & 1;
            *(uint4*)&Ts[nb][row][seg] = make_uint4(pk2(pa[0].x, pa[0].y), pk2(pa[0].z, pa[0].w),
                                                    pk2(pa[1].x, pa[1].y), pk2(pa[1].z, pa[1].w));
            *(uint4*)&Ts[nb][row][seg + 8] = make_uint4(pk2(pa[2].x, pa[2].y), pk2(pa[2].z, pa[2].w),
                                                        pk2(pa[3].x, pa[3].y), pk2(pa[3].z, pa[3].w));
        }
    }

    const int r = lane >> 2, cpr = (lane & 3) * 2;
#pragma unroll
    for (int i = 0; i < 4; i++)
#pragma unroll
        for (int j = 0; j < 4; j++) {
            int gi = 128 + m0 + i * 16 + r;
            int gj = 128 + n0 + j * 8 + cpr;
            atomicAdd(&g_gram[gi * C_DIM + gj], acc[i][j][0]);
            atomicAdd(&g_gram[gi * C_DIM + gj + 1], acc[i][j][1]);
            atomicAdd(&g_gram[(gi + 8) * C_DIM + gj], acc[i][j][2]);
            atomicAdd(&g_gram[(gi + 8) * C_DIM + gj + 1], acc[i][j][3]);
        }
}

// ---------------- buildA (fused trace): quadrants Q00, Q10 (mirror->Q01), Q11 ----------------
__global__ void buildA_kernel() {
    __shared__ float red[256];
    const float invm = 1.f / (float)M_TOT;
    int t = threadIdx.x;
    {
        float mu = g_mean[t] * invm;
        red[t] = g_gram[t * (C_DIM + 1)] * invm - mu * mu + EPSV;
    }
    __syncthreads();
    for (int s = 128; s > 0; s >>= 1) {
        if (t < s) red[t] += red[t + s];
        __syncthreads();
    }
    float sv = red[0] / (float)C_DIM;
    float invs = 1.f / sv;
    if (blockIdx.x == 0 && t == 0) g_scal[0] = rsqrtf(sv);

    int base = blockIdx.x * 1024 + t * 4;
#pragma unroll
    for (int u = 0; u < 4; u++) {
        int idx = base + u;
        int q = idx >> 14, rr = idx & 16383;
        int i, j;
        if (q == 0)      { i = rr >> 7;         j = rr & 127; }
        else if (q == 1) { i = 128 + (rr >> 7); j = rr & 127; }
        else             { i = 128 + (rr >> 7); j = 128 + (rr & 127); }
        float sig = g_gram[i * C_DIM + j] * invm - (g_mean[i] * invm) * (g_mean[j] * invm);
        if (i == j) sig += EPSV;
        float v = sig * invs - ((i == j) ? 1.f : 0.f);
        g_A[i * C_DIM + j] = v;
        if (q == 1) g_A[j * C_DIM + i] = v;
    }
}

// ---------------- small fp32 64x64-tile GEMM core, K range [kb, ke) ----------------
__device__ __forceinline__ void small_gemm64(const float* __restrict__ A, const float* __restrict__ B,
                                             float acc[4][4], int i0, int j0, int kb, int ke) {
    __shared__ float As[16][68];
    __shared__ float Bs[16][68];
    const int tid = threadIdx.x;
    const int tx = tid & 15, ty = tid >> 4;
    const int arow = tid >> 2, akq = (tid & 3) * 4;
    for (int k0 = kb; k0 < ke; k0 += 16) {
        __syncthreads();
        float4 va = *(const float4*)&A[(i0 + arow) * C_DIM + k0 + akq];
        As[akq + 0][arow] = va.x; As[akq + 1][arow] = va.y;
        As[akq + 2][arow] = va.z; As[akq + 3][arow] = va.w;
        float4 vb = *(const float4*)&B[(k0 + ty) * C_DIM + j0 + tx * 4];
        *(float4*)&Bs[ty][tx * 4] = vb;
        __syncthreads();
#pragma unroll
        for (int k = 0; k < 16; k++) {
            float4 a = *(const float4*)&As[k][ty * 4];
            float4 b = *(const float4*)&Bs[k][tx * 4];
            float av[4] = {a.x, a.y, a.z, a.w};
            float bv[4] = {b.x, b.y, b.z, b.w};
#pragma unroll
            for (int r = 0; r < 4; r++)
#pragma unroll
                for (int c = 0; c < 4; c++) acc[r][c] = fmaf(av[r], bv[c], acc[r][c]);
        }
    }
}

// ---------------- A2 = A@A, split-K x4, atomic accumulate ----------------
__global__ void pgemmA2_kernel() {
    int i0 = blockIdx.y * 64, j0 = blockIdx.x * 64, z = blockIdx.z;
    float acc[4][4] = {};
    small_gemm64(g_A, g_A, acc, i0, j0, z * 64, z * 64 + 64);
    int tx = threadIdx.x & 15, ty = threadIdx.x >> 4;
#pragma unroll
    for (int r = 0; r < 4; r++)
#pragma unroll
        for (int c = 0; c < 4; c++)
            atomicAdd(&g_A2[(i0 + ty * 4 + r) * C_DIM + j0 + tx * 4 + c], acc[r][c]);
}

// ---------------- final: acc = Q@A2 with Q built in the A-tile load ----------------
__global__ void final_gemm_kernel() {
    const float c1 = -0.5f, c2 = 0.375f, c3 = -0.3125f, c4 = 0.2734375f;
    __shared__ float As[16][68];
    __shared__ float Bs[16][68];
    int i0 = blockIdx.y * 64, j0 = blockIdx.x * 64;
    const int tid = threadIdx.x;
    const int tx = tid & 15, ty = tid >> 4;
    const int arow = tid >> 2, akq = (tid & 3) * 4;
    float acc[4][4] = {};

    for (int k0 = 0; k0 < C_DIM; k0 += 16) {
        __syncthreads();
        int gi = i0 + arow, gk = k0 + akq;
        float4 a1 = *(const float4*)&g_A[gi * C_DIM + gk];
        float4 a2 = *(const float4*)&g_A2[gi * C_DIM + gk];
        As[akq + 0][arow] = c3 * a1.x + c4 * a2.x + ((gi == gk + 0) ? c2 : 0.f);
        As[akq + 1][arow] = c3 * a1.y + c4 * a2.y + ((gi == gk + 1) ? c2 : 0.f);
        As[akq + 2][arow] = c3 * a1.z + c4 * a2.z + ((gi == gk + 2) ? c2 : 0.f);
        As[akq + 3][arow] = c3 * a1.w + c4 * a2.w + ((gi == gk + 3) ? c2 : 0.f);
        float4 vb = *(const float4*)&g_A2[(k0 + ty) * C_DIM + j0 + tx * 4];
        *(float4*)&Bs[ty][tx * 4] = vb;
        __syncthreads();
#pragma unroll
        for (int k = 0; k < 16; k++) {
            float4 a = *(const float4*)&As[k][ty * 4];
            float4 b = *(const float4*)&Bs[k][tx * 4];
            float av[4] = {a.x, a.y, a.z, a.w};
            float bv[4] = {b.x, b.y, b.z, b.w};
#pragma unroll
            for (int r = 0; r < 4; r++)
#pragma unroll
                for (int c = 0; c < 4; c++) acc[r][c] = fmaf(av[r], bv[c], acc[r][c]);
        }
    }

    float rs = g_scal[0];
    const float invm = 1.f / (float)M_TOT;
#pragma unroll
    for (int r = 0; r < 4; r++) {
        int gi = i0 + ty * 4 + r;
        float bsum = 0.f;
#pragma unroll
        for (int c = 0; c < 4; c++) {
            int gj = j0 + tx * 4 + c;
            float d = (gi == gj) ? 1.f : 0.f;
            float w = rs * (d + c1 * g_A[gi * C_DIM + gj] + acc[r][c]);
            g_Wb[gi * C_DIM + gj] = __float2bfloat16(w - d);
            bsum += w * (g_mean[gj] * invm);
        }
        atomicAdd(&g_bias[gi], bsum);
    }
}

// ---------------- apply: out = (wm-I)@bf16(X) + X - bias ; M=256 tile (R12 form verbatim) ----------------
#define APPLY_SMEM (2 * 256 * 40 * 2 + 2 * 32 * 136 * 2)   // 58368 bytes
__global__ __launch_bounds__(512, 1) void apply_kernel(const float* __restrict__ X,
                                                       float* __restrict__ out) {
    extern __shared__ __align__(16) char sm[];
    __nv_bfloat16 (*As)[40] = (__nv_bfloat16 (*)[40])sm;
    __nv_bfloat16 (*Bs)[136] = (__nv_bfloat16 (*)[136])(sm + 2 * 256 * 40 * 2);
    const int l0 = blockIdx.x * 128, n = blockIdx.y;
    const int tid = threadIdx.x, wid = tid >> 5, lane = tid & 31;
    const int m0 = (wid >> 2) * 64, n0 = (wid & 3) * 32;
    const int arow = tid >> 1, aseg = (tid & 1) * 16;
    const int brow = tid >> 4, bcol = (tid & 15) * 8;

    const __nv_bfloat16* Ag = g_Wb + arow * C_DIM + aseg;
    const float* Bg = X + ((size_t)(n * C_DIM + brow)) * L_DIM + l0 + bcol;

    float acc[4][4][4];
#pragma unroll
    for (int i = 0; i < 4; i++)
#pragma unroll
        for (int j = 0; j < 4; j++)
#pragma unroll
            for (int r = 0; r < 4; r++) acc[i][j][r] = 0.f;

    uint32_t sA0 = smem_u32(&As[arow][aseg]);
    const uint32_t aStride = 256 * 40 * 2;
    float4 pb0, pb1;

    cp16(sA0, Ag);
    cp16(sA0 + 16, Ag + 8);
    pb0 = *(const float4*)(Bg);
    pb1 = *(const float4*)(Bg + 4);
    cp_commit();
    *(uint4*)&Bs[brow][bcol] = make_uint4(pk2(pb0.x, pb0.y), pk2(pb0.z, pb0.w),
                                          pk2(pb1.x, pb1.y), pk2(pb1.z, pb1.w));

#pragma unroll 1
    for (int c = 0; c < 8; c++) {
        const bool more = (c + 1 < 8);
        if (more) {
            int k0n = (c + 1) * 32;
            int nb = (c + 1) & 1;
            cp16(sA0 + nb * aStride, Ag + k0n);
            cp16(sA0 + nb * aStride + 16, Ag + k0n + 8);
            pb0 = *(const float4*)(Bg + (size_t)k0n * L_DIM);
            pb1 = *(const float4*)(Bg + (size_t)k0n * L_DIM + 4);
            cp_commit();
            cp_wait<1>();
        } else {
            cp_wait<0>();
        }
        __syncthreads();
        const int buf = c & 1;
#pragma unroll
        for (int ks = 0; ks < 2; ks++) {
            uint32_t af[4][4], bq[4][2];
#pragma unroll
            for (int i = 0; i < 4; i++)
                ldsm4(af[i], smem_u32(&As[buf * 256 + m0 + i * 16 + (lane & 15)][ks * 16 + ((lane >> 4) << 3)]));
#pragma unroll
            for (int j = 0; j < 4; j++)
                ldsm2t(bq[j], smem_u32(&Bs[buf * 32 + ks * 16 + (lane & 15)][n0 + j * 8]));
#pragma unroll
            for (int i = 0; i < 4; i++)
#pragma unroll
                for (int j = 0; j < 4; j++) mma_bf16(acc[i][j], af[i], bq[j]);
        }
        if (more) {
            int nb = (c + 1) & 1;
            *(uint4*)&Bs[nb * 32 + brow][bcol] = make_uint4(pk2(pb0.x, pb0.y), pk2(pb0.z, pb0.w),
                                                            pk2(pb1.x, pb1.y), pk2(pb1.z, pb1.w));
        }
    }

    const int r = lane >> 2, cpr = (lane & 3) * 2;
#pragma unroll
    for (int i = 0; i < 4; i++) {
        int c_ = m0 + i * 16 + r;
        float b0 = g_bias[c_], b1 = g_bias[c_ + 8];
        const float* x0 = X + ((size_t)(n * C_DIM + c_)) * L_DIM + l0;
        const float* x1 = x0 + (size_t)8 * L_DIM;
        float* o0 = out + ((size_t)(n * C_DIM + c_)) * L_DIM + l0;
        float* o1 = o0 + (size_t)8 * L_DIM;
#pragma unroll
        for (int j = 0; j < 4; j++) {
            int l = n0 + j * 8 + cpr;
            float2 xv0 = *(const float2*)(x0 + l);
            float2 xv1 = *(const float2*)(x1 + l);
            float2 ov0 = make_float2(acc[i][j][0] + xv0.x - b0, acc[i][j][1] + xv0.y - b0);
            float2 ov1 = make_float2(acc[i][j][2] + xv1.x - b1, acc[i][j][3] + xv1.y - b1);
            *(float2*)(o0 + l) = ov0;
            *(float2*)(o1 + l) = ov1;
        }
    }
}

// ---------------- launch ----------------
extern "C" void kernel_launch(void* const* d_in, const int* in_sizes, int n_in,
                              void* d_out, int out_size) {
    const float* X = (const float*)d_in[0];
    float* out = (float*)d_out;

    cudaFuncSetAttribute(apply_kernel, cudaFuncAttributeMaxDynamicSharedMemorySize, APPLY_SMEM);

    zero_kernel<<<64, 256>>>();
    gramL_kernel<<<dim3(N_DIM, 4), 512>>>(X);

    // gramD is fully independent of gramL: launch with Programmatic Stream
    // Serialization so its CTAs can fill gramL's tail wave. Fallback = normal launch.
    {
        cudaLaunchConfig_t cfg = {};
        cfg.gridDim = dim3(N_DIM, 4);
        cfg.blockDim = dim3(256);
        cfg.dynamicSmemBytes = 0;
        cfg.stream = 0;
        cudaLaunchAttribute attrs[1];
        attrs[0].id = cudaLaunchAttributeProgrammaticStreamSerialization;
        attrs[0].val.programmaticStreamSerializationAllowed = 1;
        cfg.attrs = attrs;
        cfg.numAttrs = 1;
        cudaError_t e = cudaLaunchKernelEx(&cfg, gramD_kernel, X);
        if (e != cudaSuccess) {
            (void)cudaGetLastError();   // clear sticky error
            gramD_kernel<<<dim3(N_DIM, 4), 256>>>(X);
        }
    }

    buildA_kernel<<<48, 256>>>();
    pgemmA2_kernel<<<dim3(4, 4, 4), 256>>>();
    final_gemm_kernel<<<dim3(4, 4), 256>>>();
    apply_kernel<<<dim3(32, N_DIM), 512, APPLY_SMEM>>>(X, out);
}

// round 16
// speedup vs baseline: 1.0683x; 1.0055x over previous
#include <cuda_runtime.h>
#include <cuda_bf16.h>
#include <cstdint>
#include <cstddef>

#define C_DIM 256
#define L_DIM 4096
#define N_DIM 64
#define M_TOT (N_DIM * L_DIM)   // 262144
#define EPSV 1e-3f

// ---------------- scratch (device globals) ----------------
__device__ __nv_bfloat16 g_Wb[C_DIM * C_DIM];   // bf16 (wm - I)
__device__ float g_mean[C_DIM];                 // raw channel sums
__device__ float g_gram[C_DIM * C_DIM];         // raw X X^T sums (Q00, Q10, Q11 used)
__device__ float g_A[C_DIM * C_DIM];
__device__ float g_A2[C_DIM * C_DIM];           // atomic accum: A@A
__device__ float g_bias[C_DIM];
__device__ float g_scal[1];                     // rsqrt(s)

// ---------------- low-level helpers ----------------
__device__ __forceinline__ uint32_t smem_u32(const void* p) {
    return (uint32_t)__cvta_generic_to_shared(p);
}
__device__ __forceinline__ void cp16(uint32_t saddr, const void* g) {
    asm volatile("cp.async.cg.shared.global [%0], [%1], 16;\n" :: "r"(saddr), "l"(g));
}
__device__ __forceinline__ void cp_commit() { asm volatile("cp.async.commit_group;\n"); }
template<int N> __device__ __forceinline__ void cp_wait() {
    asm volatile("cp.async.wait_group %0;\n" :: "n"(N));
}
__device__ __forceinline__ void ldsm4(uint32_t r[4], uint32_t a) {
    asm volatile("ldmatrix.sync.aligned.m8n8.x4.shared.b16 {%0,%1,%2,%3}, [%4];"
                 : "=r"(r[0]), "=r"(r[1]), "=r"(r[2]), "=r"(r[3]) : "r"(a));
}
__device__ __forceinline__ void ldsm2(uint32_t r[2], uint32_t a) {
    asm volatile("ldmatrix.sync.aligned.m8n8.x2.shared.b16 {%0,%1}, [%2];"
                 : "=r"(r[0]), "=r"(r[1]) : "r"(a));
}
__device__ __forceinline__ void ldsm2t(uint32_t r[2], uint32_t a) {
    asm volatile("ldmatrix.sync.aligned.m8n8.x2.trans.shared.b16 {%0,%1}, [%2];"
                 : "=r"(r[0]), "=r"(r[1]) : "r"(a));
}
__device__ __forceinline__ void mma_bf16(float d[4], const uint32_t a[4], const uint32_t b[2]) {
    asm volatile("mma.sync.aligned.m16n8k16.row.col.f32.bf16.bf16.f32 "
                 "{%0,%1,%2,%3}, {%4,%5,%6,%7}, {%8,%9}, {%0,%1,%2,%3};"
                 : "+f"(d[0]), "+f"(d[1]), "+f"(d[2]), "+f"(d[3])
                 : "r"(a[0]), "r"(a[1]), "r"(a[2]), "r"(a[3]), "r"(b[0]), "r"(b[1]));
}
__device__ __forceinline__ uint32_t pk2(float x, float y) {
    __nv_bfloat162 h = __floats2bfloat162_rn(x, y);
    return *(uint32_t*)&h;
}

// ---------------- zero accumulators (vectorized) ----------------
__global__ void zero_kernel() {
    int idx = blockIdx.x * 256 + threadIdx.x;    // 64 blocks -> 16384 threads
    float4 z = make_float4(0.f, 0.f, 0.f, 0.f);
    *(float4*)&g_gram[idx * 4] = z;
    *(float4*)&g_A2[idx * 4] = z;
    if (idx < C_DIM) { g_mean[idx] = 0.f; g_bias[idx] = 0.f; }
}

// ---------------- gramL: left half (rows 0..255) x (cols 0..127), ONE shared tile ----------------
__global__ __launch_bounds__(512, 1) void gramL_kernel(const float* __restrict__ X) {
    // PDL: allow the dependent gramD launch as soon as every gramL CTA has started.
    cudaTriggerProgrammaticLaunchCompletion();

    __shared__ __align__(16) __nv_bfloat16 Ts[2][256][40];
    const int n = blockIdx.x, zh = blockIdx.y;
    const int tid = threadIdx.x, wid = tid >> 5, lane = tid & 31;
    const int m0 = (wid >> 2) * 64, n0 = (wid & 3) * 32;
    const int row = tid >> 1, seg = (tid & 1) * 16;

    const float* Ag = X + ((size_t)(n * C_DIM + row)) * L_DIM + zh * 1024 + seg;

    float acc[4][4][4];
#pragma unroll
    for (int i = 0; i < 4; i++)
#pragma unroll
        for (int j = 0; j < 4; j++)
#pragma unroll
            for (int r = 0; r < 4; r++) acc[i][j][r] = 0.f;
    float msum = 0.f;
    float4 pa[4];

#pragma unroll
    for (int q = 0; q < 4; q++) pa[q] = *(const float4*)(Ag + q * 4);
    msum += (pa[0].x + pa[0].y + pa[0].z + pa[0].w) + (pa[1].x + pa[1].y + pa[1].z + pa[1].w)
          + (pa[2].x + pa[2].y + pa[2].z + pa[2].w) + (pa[3].x + pa[3].y + pa[3].z + pa[3].w);
    *(uint4*)&Ts[0][row][seg] = make_uint4(pk2(pa[0].x, pa[0].y), pk2(pa[0].z, pa[0].w),
                                           pk2(pa[1].x, pa[1].y), pk2(pa[1].z, pa[1].w));
    *(uint4*)&Ts[0][row][seg + 8] = make_uint4(pk2(pa[2].x, pa[2].y), pk2(pa[2].z, pa[2].w),
                                               pk2(pa[3].x, pa[3].y), pk2(pa[3].z, pa[3].w));

#pragma unroll 1
    for (int c = 0; c < 32; c++) {
        __syncthreads();
        const bool more = (c + 1 < 32);
        if (more) {
#pragma unroll
            for (int q = 0; q < 4; q++) pa[q] = *(const float4*)(Ag + (c + 1) * 32 + q * 4);
        }
        const int buf = c & 1;
#pragma unroll
        for (int ks = 0; ks < 2; ks++) {
            uint32_t af[4][4], bq[4][2];
#pragma unroll
            for (int i = 0; i < 4; i++)
                ldsm4(af[i], smem_u32(&Ts[buf][m0 + i * 16 + (lane & 15)][ks * 16 + ((lane >> 4) << 3)]));
#pragma unroll
            for (int j = 0; j < 4; j++)
                ldsm2(bq[j], smem_u32(&Ts[buf][n0 + j * 8 + (lane & 7)][ks * 16 + (lane & 8)]));
#pragma unroll
            for (int i = 0; i < 4; i++)
#pragma unroll
                for (int j = 0; j < 4; j++) mma_bf16(acc[i][j], af[i], bq[j]);
        }
        if (more) {
            const int nb = (c + 1) & 1;
            msum += (pa[0].x + pa[0].y + pa[0].z + pa[0].w) + (pa[1].x + pa[1].y + pa[1].z + pa[1].w)
                  + (pa[2].x + pa[2].y + pa[2].z + pa[2].w) + (pa[3].x + pa[3].y + pa[3].z + pa[3].w);
            *(uint4*)&Ts[nb][row][seg] = make_uint4(pk2(pa[0].x, pa[0].y), pk2(pa[0].z, pa[0].w),
                                                    pk2(pa[1].x, pa[1].y), pk2(pa[1].z, pa[1].w));
            *(uint4*)&Ts[nb][row][seg + 8] = make_uint4(pk2(pa[2].x, pa[2].y), pk2(pa[2].z, pa[2].w),
                                                        pk2(pa[3].x, pa[3].y), pk2(pa[3].z, pa[3].w));
        }
    }

    atomicAdd(&g_mean[row], msum);

    const int r = lane >> 2, cpr = (lane & 3) * 2;
#pragma unroll
    for (int i = 0; i < 4; i++)
#pragma unroll
        for (int j = 0; j < 4; j++) {
            int gi = m0 + i * 16 + r;
            int gj = n0 + j * 8 + cpr;
            atomicAdd(&g_gram[gi * C_DIM + gj], acc[i][j][0]);
            atomicAdd(&g_gram[gi * C_DIM + gj + 1], acc[i][j][1]);
            atomicAdd(&g_gram[(gi + 8) * C_DIM + gj], acc[i][j][2]);
            atomicAdd(&g_gram[(gi + 8) * C_DIM + gj + 1], acc[i][j][3]);
        }
}

// ---------------- gramD: Q11 diagonal block (rows/cols 128..255), A=B one tile ----------------
__global__ __launch_bounds__(256, 2) void gramD_kernel(const float* __restrict__ X) {
    __shared__ __align__(16) __nv_bfloat16 Ts[2][128][40];
    const int n = blockIdx.x, zh = blockIdx.y;
    const int tid = threadIdx.x, wid = tid >> 5, lane = tid & 31;
    const int m0 = (wid >> 2) * 64, n0 = (wid & 3) * 32;
    const int row = tid >> 1, seg = (tid & 1) * 16;

    const float* Ag = X + ((size_t)(n * C_DIM + 128 + row)) * L_DIM + zh * 1024 + seg;

    float acc[4][4][4];
#pragma unroll
    for (int i = 0; i < 4; i++)
#pragma unroll
        for (int j = 0; j < 4; j++)
#pragma unroll
            for (int r = 0; r < 4; r++) acc[i][j][r] = 0.f;
    float4 pa[4];

#pragma unroll
    for (int q = 0; q < 4; q++) pa[q] = *(const float4*)(Ag + q * 4);
    *(uint4*)&Ts[0][row][seg] = make_uint4(pk2(pa[0].x, pa[0].y), pk2(pa[0].z, pa[0].w),
                                           pk2(pa[1].x, pa[1].y), pk2(pa[1].z, pa[1].w));
    *(uint4*)&Ts[0][row][seg + 8] = make_uint4(pk2(pa[2].x, pa[2].y), pk2(pa[2].z, pa[2].w),
                                               pk2(pa[3].x, pa[3].y), pk2(pa[3].z, pa[3].w));

#pragma unroll 1
    for (int c = 0; c < 32; c++) {
        __syncthreads();
        const bool more = (c + 1 < 32);
        if (more) {
#pragma unroll
            for (int q = 0; q < 4; q++) pa[q] = *(const float4*)(Ag + (c + 1) * 32 + q * 4);
        }
        const int buf = c & 1;
#pragma unroll
        for (int ks = 0; ks < 2; ks++) {
            uint32_t af[4][4], bq[4][2];
#pragma unroll
            for (int i = 0; i < 4; i++)
                ldsm4(af[i], smem_u32(&Ts[buf][m0 + i * 16 + (lane & 15)][ks * 16 + ((lane >> 4) << 3)]));
#pragma unroll
            for (int j = 0; j < 4; j++)
                ldsm2(bq[j], smem_u32(&Ts[buf][n0 + j * 8 + (lane & 7)][ks * 16 + (lane & 8)]));
#pragma unroll
            for (int i = 0; i < 4; i++)
#pragma unroll
                for (int j = 0; j < 4; j++) mma_bf16(acc[i][j], af[i], bq[j]);
        }
        if (more) {
            const int nb = (c + 1) & 1;
            *(uint4*)&Ts[nb][row][seg] = make_uint4(pk2(pa[0].x, pa[0].y), pk2(pa[0].z, pa[0].w),
                                                    pk2(pa[1].x, pa[1].y), pk2(pa[1].z, pa[1].w));
            *(uint4*)&Ts[nb][row][seg + 8] = make_uint4(pk2(pa[2].x, pa[2].y), pk2(pa[2].z, pa[2].w),
                                                        pk2(pa[3].x, pa[3].y), pk2(pa[3].z, pa[3].w));
        }
    }

    const int r = lane >> 2, cpr = (lane & 3) * 2;
#pragma unroll
    for (int i = 0; i < 4; i++)
#pragma unroll
        for (int j = 0; j < 4; j++) {
            int gi = 128 + m0 + i * 16 + r;
            int gj = 128 + n0 + j * 8 + cpr;
            atomicAdd(&g_gram[gi * C_DIM + gj], acc[i][j][0]);
            atomicAdd(&g_gram[gi * C_DIM + gj + 1], acc[i][j][1]);
            atomicAdd(&g_gram[(gi + 8) * C_DIM + gj], acc[i][j][2]);
            atomicAdd(&g_gram[(gi + 8) * C_DIM + gj + 1], acc[i][j][3]);
        }
}

// ---------------- buildA (fused trace): quadrants Q00, Q10 (mirror->Q01), Q11 ----------------
__global__ void buildA_kernel() {
    __shared__ float red[256];
    const float invm = 1.f / (float)M_TOT;
    int t = threadIdx.x;
    {
        float mu = g_mean[t] * invm;
        red[t] = g_gram[t * (C_DIM + 1)] * invm - mu * mu + EPSV;
    }
    __syncthreads();
    for (int s = 128; s > 0; s >>= 1) {
        if (t < s) red[t] += red[t + s];
        __syncthreads();
    }
    float sv = red[0] / (float)C_DIM;
    float invs = 1.f / sv;
    if (blockIdx.x == 0 && t == 0) g_scal[0] = rsqrtf(sv);

    int base = blockIdx.x * 1024 + t * 4;
#pragma unroll
    for (int u = 0; u < 4; u++) {
        int idx = base + u;
        int q = idx >> 14, rr = idx & 16383;
        int i, j;
        if (q == 0)      { i = rr >> 7;         j = rr & 127; }
        else if (q == 1) { i = 128 + (rr >> 7); j = rr & 127; }
        else             { i = 128 + (rr >> 7); j = 128 + (rr & 127); }
        float sig = g_gram[i * C_DIM + j] * invm - (g_mean[i] * invm) * (g_mean[j] * invm);
        if (i == j) sig += EPSV;
        float v = sig * invs - ((i == j) ? 1.f : 0.f);
        g_A[i * C_DIM + j] = v;
        if (q == 1) g_A[j * C_DIM + i] = v;
    }
}

// ---------------- small fp32 64x64-tile GEMM core, K range [kb, ke) ----------------
__device__ __forceinline__ void small_gemm64(const float* __restrict__ A, const float* __restrict__ B,
                                             float acc[4][4], int i0, int j0, int kb, int ke) {
    __shared__ float As[16][68];
    __shared__ float Bs[16][68];
    const int tid = threadIdx.x;
    const int tx = tid & 15, ty = tid >> 4;
    const int arow = tid >> 2, akq = (tid & 3) * 4;
    for (int k0 = kb; k0 < ke; k0 += 16) {
        __syncthreads();
        float4 va = *(const float4*)&A[(i0 + arow) * C_DIM + k0 + akq];
        As[akq + 0][arow] = va.x; As[akq + 1][arow] = va.y;
        As[akq + 2][arow] = va.z; As[akq + 3][arow] = va.w;
        float4 vb = *(const float4*)&B[(k0 + ty) * C_DIM + j0 + tx * 4];
        *(float4*)&Bs[ty][tx * 4] = vb;
        __syncthreads();
#pragma unroll
        for (int k = 0; k < 16; k++) {
            float4 a = *(const float4*)&As[k][ty * 4];
            float4 b = *(const float4*)&Bs[k][tx * 4];
            float av[4] = {a.x, a.y, a.z, a.w};
            float bv[4] = {b.x, b.y, b.z, b.w};
#pragma unroll
            for (int r = 0; r < 4; r++)
#pragma unroll
                for (int c = 0; c < 4; c++) acc[r][c] = fmaf(av[r], bv[c], acc[r][c]);
        }
    }
}

// ---------------- A2 = A@A, split-K x4, atomic accumulate ----------------
__global__ void pgemmA2_kernel() {
    int i0 = blockIdx.y * 64, j0 = blockIdx.x * 64, z = blockIdx.z;
    float acc[4][4] = {};
    small_gemm64(g_A, g_A, acc, i0, j0, z * 64, z * 64 + 64);
    int tx = threadIdx.x & 15, ty = threadIdx.x >> 4;
#pragma unroll
    for (int r = 0; r < 4; r++)
#pragma unroll
        for (int c = 0; c < 4; c++)
            atomicAdd(&g_A2[(i0 + ty * 4 + r) * C_DIM + j0 + tx * 4 + c], acc[r][c]);
}

// ---------------- final: acc = Q@A2 with Q built in the A-tile load ----------------
__global__ void final_gemm_kernel() {
    const float c1 = -0.5f, c2 = 0.375f, c3 = -0.3125f, c4 = 0.2734375f;
    __shared__ float As[16][68];
    __shared__ float Bs[16][68];
    int i0 = blockIdx.y * 64, j0 = blockIdx.x * 64;
    const int tid = threadIdx.x;
    const int tx = tid & 15, ty = tid >> 4;
    const int arow = tid >> 2, akq = (tid & 3) * 4;
    float acc[4][4] = {};

    for (int k0 = 0; k0 < C_DIM; k0 += 16) {
        __syncthreads();
        int gi = i0 + arow, gk = k0 + akq;
        float4 a1 = *(const float4*)&g_A[gi * C_DIM + gk];
        float4 a2 = *(const float4*)&g_A2[gi * C_DIM + gk];
        As[akq + 0][arow] = c3 * a1.x + c4 * a2.x + ((gi == gk + 0) ? c2 : 0.f);
        As[akq + 1][arow] = c3 * a1.y + c4 * a2.y + ((gi == gk + 1) ? c2 : 0.f);
        As[akq + 2][arow] = c3 * a1.z + c4 * a2.z + ((gi == gk + 2) ? c2 : 0.f);
        As[akq + 3][arow] = c3 * a1.w + c4 * a2.w + ((gi == gk + 3) ? c2 : 0.f);
        float4 vb = *(const float4*)&g_A2[(k0 + ty) * C_DIM + j0 + tx * 4];
        *(float4*)&Bs[ty][tx * 4] = vb;
        __syncthreads();
#pragma unroll
        for (int k = 0; k < 16; k++) {
            float4 a = *(const float4*)&As[k][ty * 4];
            float4 b = *(const float4*)&Bs[k][tx * 4];
            float av[4] = {a.x, a.y, a.z, a.w};
            float bv[4] = {b.x, b.y, b.z, b.w};
#pragma unroll
            for (int r = 0; r < 4; r++)
#pragma unroll
                for (int c = 0; c < 4; c++) acc[r][c] = fmaf(av[r], bv[c], acc[r][c]);
        }
    }

    float rs = g_scal[0];
    const float invm = 1.f / (float)M_TOT;
#pragma unroll
    for (int r = 0; r < 4; r++) {
        int gi = i0 + ty * 4 + r;
        float bsum = 0.f;
#pragma unroll
        for (int c = 0; c < 4; c++) {
            int gj = j0 + tx * 4 + c;
            float d = (gi == gj) ? 1.f : 0.f;
            float w = rs * (d + c1 * g_A[gi * C_DIM + gj] + acc[r][c]);
            g_Wb[gi * C_DIM + gj] = __float2bfloat16(w - d);
            bsum += w * (g_mean[gj] * invm);
        }
        atomicAdd(&g_bias[gi], bsum);
    }
}

// ---------------- apply: out = (wm-I)@bf16(X) + X - bias ; M=256 tile (R12 form verbatim) ----------------
#define APPLY_SMEM (2 * 256 * 40 * 2 + 2 * 32 * 136 * 2)   // 58368 bytes
__global__ __launch_bounds__(512, 1) void apply_kernel(const float* __restrict__ X,
                                                       float* __restrict__ out) {
    extern __shared__ __align__(16) char sm[];
    __nv_bfloat16 (*As)[40] = (__nv_bfloat16 (*)[40])sm;
    __nv_bfloat16 (*Bs)[136] = (__nv_bfloat16 (*)[136])(sm + 2 * 256 * 40 * 2);
    const int l0 = blockIdx.x * 128, n = blockIdx.y;
    const int tid = threadIdx.x, wid = tid >> 5, lane = tid & 31;
    const int m0 = (wid >> 2) * 64, n0 = (wid & 3) * 32;
    const int arow = tid >> 1, aseg = (tid & 1) * 16;
    const int brow = tid >> 4, bcol = (tid & 15) * 8;

    const __nv_bfloat16* Ag = g_Wb + arow * C_DIM + aseg;
    const float* Bg = X + ((size_t)(n * C_DIM + brow)) * L_DIM + l0 + bcol;

    float acc[4][4][4];
#pragma unroll
    for (int i = 0; i < 4; i++)
#pragma unroll
        for (int j = 0; j < 4; j++)
#pragma unroll
            for (int r = 0; r < 4; r++) acc[i][j][r] = 0.f;

    uint32_t sA0 = smem_u32(&As[arow][aseg]);
    const uint32_t aStride = 256 * 40 * 2;
    float4 pb0, pb1;

    cp16(sA0, Ag);
    cp16(sA0 + 16, Ag + 8);
    pb0 = *(const float4*)(Bg);
    pb1 = *(const float4*)(Bg + 4);
    cp_commit();
    *(uint4*)&Bs[brow][bcol] = make_uint4(pk2(pb0.x, pb0.y), pk2(pb0.z, pb0.w),
                                          pk2(pb1.x, pb1.y), pk2(pb1.z, pb1.w));

#pragma unroll 1
    for (int c = 0; c < 8; c++) {
        const bool more = (c + 1 < 8);
        if (more) {
            int k0n = (c + 1) * 32;
            int nb = (c + 1) & 1;
            cp16(sA0 + nb * aStride, Ag + k0n);
            cp16(sA0 + nb * aStride + 16, Ag + k0n + 8);
            pb0 = *(const float4*)(Bg + (size_t)k0n * L_DIM);
            pb1 = *(const float4*)(Bg + (size_t)k0n * L_DIM + 4);
            cp_commit();
            cp_wait<1>();
        } else {
            cp_wait<0>();
        }
        __syncthreads();
        const int buf = c & 1;
#pragma unroll
        for (int ks = 0; ks < 2; ks++) {
            uint32_t af[4][4], bq[4][2];
#pragma unroll
            for (int i = 0; i < 4; i++)
                ldsm4(af[i], smem_u32(&As[buf * 256 + m0 + i * 16 + (lane & 15)][ks * 16 + ((lane >> 4) << 3)]));
#pragma unroll
            for (int j = 0; j < 4; j++)
                ldsm2t(bq[j], smem_u32(&Bs[buf * 32 + ks * 16 + (lane & 15)][n0 + j * 8]));
#pragma unroll
            for (int i = 0; i < 4; i++)
#pragma unroll
                for (int j = 0; j < 4; j++) mma_bf16(acc[i][j], af[i], bq[j]);
        }
        if (more) {
            int nb = (c + 1) & 1;
            *(uint4*)&Bs[nb * 32 + brow][bcol] = make_uint4(pk2(pb0.x, pb0.y), pk2(pb0.z, pb0.w),
                                                            pk2(pb1.x, pb1.y), pk2(pb1.z, pb1.w));
        }
    }

    const int r = lane >> 2, cpr = (lane & 3) * 2;
#pragma unroll
    for (int i = 0; i < 4; i++) {
        int c_ = m0 + i * 16 + r;
        float b0 = g_bias[c_], b1 = g_bias[c_ + 8];
        const float* x0 = X + ((size_t)(n * C_DIM + c_)) * L_DIM + l0;
        const float* x1 = x0 + (size_t)8 * L_DIM;
        float* o0 = out + ((size_t)(n * C_DIM + c_)) * L_DIM + l0;
        float* o1 = o0 + (size_t)8 * L_DIM;
#pragma unroll
        for (int j = 0; j < 4; j++) {
            int l = n0 + j * 8 + cpr;
            float2 xv0 = *(const float2*)(x0 + l);
            float2 xv1 = *(const float2*)(x1 + l);
            float2 ov0 = make_float2(acc[i][j][0] + xv0.x - b0, acc[i][j][1] + xv0.y - b0);
            float2 ov1 = make_float2(acc[i][j][2] + xv1.x - b1, acc[i][j][3] + xv1.y - b1);
            *(float2*)(o0 + l) = ov0;
            *(float2*)(o1 + l) = ov1;
        }
    }
}

// ---------------- launch ----------------
extern "C" void kernel_launch(void* const* d_in, const int* in_sizes, int n_in,
                              void* d_out, int out_size) {
    const float* X = (const float*)d_in[0];
    float* out = (float*)d_out;

    cudaFuncSetAttribute(apply_kernel, cudaFuncAttributeMaxDynamicSharedMemorySize, APPLY_SMEM);

    zero_kernel<<<64, 256>>>();
    gramL_kernel<<<dim3(N_DIM, 4), 512>>>(X);

    // gramD is fully independent of gramL: launch with Programmatic Stream
    // Serialization so its CTAs can fill gramL's tail wave. Fallback = normal launch.
    {
        cudaLaunchConfig_t cfg = {};
        cfg.gridDim = dim3(N_DIM, 4);
        cfg.blockDim = dim3(256);
        cfg.dynamicSmemBytes = 0;
        cfg.stream = 0;
        cudaLaunchAttribute attrs[1];
        attrs[0].id = cudaLaunchAttributeProgrammaticStreamSerialization;
        attrs[0].val.programmaticStreamSerializationAllowed = 1;
        cfg.attrs = attrs;
        cfg.numAttrs = 1;
        cudaError_t e = cudaLaunchKernelEx(&cfg, gramD_kernel, X);
        if (e != cudaSuccess) {
            (void)cudaGetLastError();   // clear sticky error
            gramD_kernel<<<dim3(N_DIM, 4), 256>>>(X);
        }
    }

    buildA_kernel<<<48, 256>>>();
    pgemmA2_kernel<<<dim3(4, 4, 4), 256>>>();
    final_gemm_kernel<<<dim3(4, 4), 256>>>();
    apply_kernel<<<dim3(32, N_DIM), 512, APPLY_SMEM>>>(X, out);
}

// round 17
// speedup vs baseline: 1.0690x; 1.0006x over previous
#include <cuda_runtime.h>
#include <cuda_bf16.h>
#include <cstdint>
#include <cstddef>

#define C_DIM 256
#define L_DIM 4096
#define N_DIM 64
#define M_TOT (N_DIM * L_DIM)   // 262144
#define EPSV 1e-3f

// ---------------- scratch (device globals) ----------------
__device__ __nv_bfloat16 g_Wb[C_DIM * C_DIM];   // bf16 (wm - I)
__device__ float g_mean[C_DIM];                 // raw channel sums
__device__ float g_gram[C_DIM * C_DIM];         // raw X X^T sums (Q00, Q10, Q11 used)
__device__ float g_A[C_DIM * C_DIM];
__device__ float g_A2[C_DIM * C_DIM];           // atomic accum: A@A
__device__ float g_bias[C_DIM];
__device__ float g_scal[1];                     // rsqrt(s)

// ---------------- low-level helpers ----------------
__device__ __forceinline__ uint32_t smem_u32(const void* p) {
    return (uint32_t)__cvta_generic_to_shared(p);
}
__device__ __forceinline__ void cp16(uint32_t saddr, const void* g) {
    asm volatile("cp.async.cg.shared.global [%0], [%1], 16;\n" :: "r"(saddr), "l"(g));
}
__device__ __forceinline__ void cp_commit() { asm volatile("cp.async.commit_group;\n"); }
template<int N> __device__ __forceinline__ void cp_wait() {
    asm volatile("cp.async.wait_group %0;\n" :: "n"(N));
}
__device__ __forceinline__ void ldsm4(uint32_t r[4], uint32_t a) {
    asm volatile("ldmatrix.sync.aligned.m8n8.x4.shared.b16 {%0,%1,%2,%3}, [%4];"
                 : "=r"(r[0]), "=r"(r[1]), "=r"(r[2]), "=r"(r[3]) : "r"(a));
}
__device__ __forceinline__ void ldsm2(uint32_t r[2], uint32_t a) {
    asm volatile("ldmatrix.sync.aligned.m8n8.x2.shared.b16 {%0,%1}, [%2];"
                 : "=r"(r[0]), "=r"(r[1]) : "r"(a));
}
__device__ __forceinline__ void ldsm2t(uint32_t r[2], uint32_t a) {
    asm volatile("ldmatrix.sync.aligned.m8n8.x2.trans.shared.b16 {%0,%1}, [%2];"
                 : "=r"(r[0]), "=r"(r[1]) : "r"(a));
}
__device__ __forceinline__ void mma_bf16(float d[4], const uint32_t a[4], const uint32_t b[2]) {
    asm volatile("mma.sync.aligned.m16n8k16.row.col.f32.bf16.bf16.f32 "
                 "{%0,%1,%2,%3}, {%4,%5,%6,%7}, {%8,%9}, {%0,%1,%2,%3};"
                 : "+f"(d[0]), "+f"(d[1]), "+f"(d[2]), "+f"(d[3])
                 : "r"(a[0]), "r"(a[1]), "r"(a[2]), "r"(a[3]), "r"(b[0]), "r"(b[1]));
}
__device__ __forceinline__ uint32_t pk2(float x, float y) {
    __nv_bfloat162 h = __floats2bfloat162_rn(x, y);
    return *(uint32_t*)&h;
}

// ---------------- zero accumulators (vectorized) ----------------
__global__ void zero_kernel() {
    int idx = blockIdx.x * 256 + threadIdx.x;    // 64 blocks -> 16384 threads
    float4 z = make_float4(0.f, 0.f, 0.f, 0.f);
    *(float4*)&g_gram[idx * 4] = z;
    *(float4*)&g_A2[idx * 4] = z;
    if (idx < C_DIM) { g_mean[idx] = 0.f; g_bias[idx] = 0.f; }
}

// ---------------- gramL: left half (rows 0..255) x (cols 0..127), ONE shared tile ----------------
__global__ __launch_bounds__(512, 1) void gramL_kernel(const float* __restrict__ X) {
    // PDL: allow the dependent gramD launch as soon as every gramL CTA has started.
    cudaTriggerProgrammaticLaunchCompletion();

    __shared__ __align__(16) __nv_bfloat16 Ts[2][256][40];
    const int n = blockIdx.x, zh = blockIdx.y;
    const int tid = threadIdx.x, wid = tid >> 5, lane = tid & 31;
    const int m0 = (wid >> 2) * 64, n0 = (wid & 3) * 32;
    const int row = tid >> 1, seg = (tid & 1) * 16;

    const float* Ag = X + ((size_t)(n * C_DIM + row)) * L_DIM + zh * 1024 + seg;

    float acc[4][4][4];
#pragma unroll
    for (int i = 0; i < 4; i++)
#pragma unroll
        for (int j = 0; j < 4; j++)
#pragma unroll
            for (int r = 0; r < 4; r++) acc[i][j][r] = 0.f;
    float msum = 0.f;
    float4 pa[4];

#pragma unroll
    for (int q = 0; q < 4; q++) pa[q] = *(const float4*)(Ag + q * 4);
    msum += (pa[0].x + pa[0].y + pa[0].z + pa[0].w) + (pa[1].x + pa[1].y + pa[1].z + pa[1].w)
          + (pa[2].x + pa[2].y + pa[2].z + pa[2].w) + (pa[3].x + pa[3].y + pa[3].z + pa[3].w);
    *(uint4*)&Ts[0][row][seg] = make_uint4(pk2(pa[0].x, pa[0].y), pk2(pa[0].z, pa[0].w),
                                           pk2(pa[1].x, pa[1].y), pk2(pa[1].z, pa[1].w));
    *(uint4*)&Ts[0][row][seg + 8] = make_uint4(pk2(pa[2].x, pa[2].y), pk2(pa[2].z, pa[2].w),
                                               pk2(pa[3].x, pa[3].y), pk2(pa[3].z, pa[3].w));

#pragma unroll 1
    for (int c = 0; c < 32; c++) {
        __syncthreads();
        const bool more = (c + 1 < 32);
        if (more) {
#pragma unroll
            for (int q = 0; q < 4; q++) pa[q] = *(const float4*)(Ag + (c + 1) * 32 + q * 4);
        }
        const int buf = c & 1;
#pragma unroll
        for (int ks = 0; ks < 2; ks++) {
            uint32_t af[4][4], bq[4][2];
#pragma unroll
            for (int i = 0; i < 4; i++)
                ldsm4(af[i], smem_u32(&Ts[buf][m0 + i * 16 + (lane & 15)][ks * 16 + ((lane >> 4) << 3)]));
#pragma unroll
            for (int j = 0; j < 4; j++)
                ldsm2(bq[j], smem_u32(&Ts[buf][n0 + j * 8 + (lane & 7)][ks * 16 + (lane & 8)]));
#pragma unroll
            for (int i = 0; i < 4; i++)
#pragma unroll
                for (int j = 0; j < 4; j++) mma_bf16(acc[i][j], af[i], bq[j]);
        }
        if (more) {
            const int nb = (c + 1) & 1;
            msum += (pa[0].x + pa[0].y + pa[0].z + pa[0].w) + (pa[1].x + pa[1].y + pa[1].z + pa[1].w)
                  + (pa[2].x + pa[2].y + pa[2].z + pa[2].w) + (pa[3].x + pa[3].y + pa[3].z + pa[3].w);
            *(uint4*)&Ts[nb][row][seg] = make_uint4(pk2(pa[0].x, pa[0].y), pk2(pa[0].z, pa[0].w),
                                                    pk2(pa[1].x, pa[1].y), pk2(pa[1].z, pa[1].w));
            *(uint4*)&Ts[nb][row][seg + 8] = make_uint4(pk2(pa[2].x, pa[2].y), pk2(pa[2].z, pa[2].w),
                                                        pk2(pa[3].x, pa[3].y), pk2(pa[3].z, pa[3].w));
        }
    }

    atomicAdd(&g_mean[row], msum);

    const int r = lane >> 2, cpr = (lane & 3) * 2;
#pragma unroll
    for (int i = 0; i < 4; i++)
#pragma unroll
        for (int j = 0; j < 4; j++) {
            int gi = m0 + i * 16 + r;
            int gj = n0 + j * 8 + cpr;
            atomicAdd(&g_gram[gi * C_DIM + gj], acc[i][j][0]);
            atomicAdd(&g_gram[gi * C_DIM + gj + 1], acc[i][j][1]);
            atomicAdd(&g_gram[(gi + 8) * C_DIM + gj], acc[i][j][2]);
            atomicAdd(&g_gram[(gi + 8) * C_DIM + gj + 1], acc[i][j][3]);
        }
}

// ---------------- gramD: Q11 diagonal block (rows/cols 128..255), A=B one tile ----------------
__global__ __launch_bounds__(256, 2) void gramD_kernel(const float* __restrict__ X) {
    __shared__ __align__(16) __nv_bfloat16 Ts[2][128][40];
    const int n = blockIdx.x, zh = blockIdx.y;
    const int tid = threadIdx.x, wid = tid >> 5, lane = tid & 31;
    const int m0 = (wid >> 2) * 64, n0 = (wid & 3) * 32;
    const int row = tid >> 1, seg = (tid & 1) * 16;

    const float* Ag = X + ((size_t)(n * C_DIM + 128 + row)) * L_DIM + zh * 1024 + seg;

    float acc[4][4][4];
#pragma unroll
    for (int i = 0; i < 4; i++)
#pragma unroll
        for (int j = 0; j < 4; j++)
#pragma unroll
            for (int r = 0; r < 4; r++) acc[i][j][r] = 0.f;
    float4 pa[4];

#pragma unroll
    for (int q = 0; q < 4; q++) pa[q] = *(const float4*)(Ag + q * 4);
    *(uint4*)&Ts[0][row][seg] = make_uint4(pk2(pa[0].x, pa[0].y), pk2(pa[0].z, pa[0].w),
                                           pk2(pa[1].x, pa[1].y), pk2(pa[1].z, pa[1].w));
    *(uint4*)&Ts[0][row][seg + 8] = make_uint4(pk2(pa[2].x, pa[2].y), pk2(pa[2].z, pa[2].w),
                                               pk2(pa[3].x, pa[3].y), pk2(pa[3].z, pa[3].w));

#pragma unroll 1
    for (int c = 0; c < 32; c++) {
        __syncthreads();
        const bool more = (c + 1 < 32);
        if (more) {
#pragma unroll
            for (int q = 0; q < 4; q++) pa[q] = *(const float4*)(Ag + (c + 1) * 32 + q * 4);
        }
        const int buf = c & 1;
#pragma unroll
        for (int ks = 0; ks < 2; ks++) {
            uint32_t af[4][4], bq[4][2];
#pragma unroll
            for (int i = 0; i < 4; i++)
                ldsm4(af[i], smem_u32(&Ts[buf][m0 + i * 16 + (lane & 15)][ks * 16 + ((lane >> 4) << 3)]));
#pragma unroll
            for (int j = 0; j < 4; j++)
                ldsm2(bq[j], smem_u32(&Ts[buf][n0 + j * 8 + (lane & 7)][ks * 16 + (lane & 8)]));
#pragma unroll
            for (int i = 0; i < 4; i++)
#pragma unroll
                for (int j = 0; j < 4; j++) mma_bf16(acc[i][j], af[i], bq[j]);
        }
        if (more) {
            const int nb = (c + 1) & 1;
            *(uint4*)&Ts[nb][row][seg] = make_uint4(pk2(pa[0].x, pa[0].y), pk2(pa[0].z, pa[0].w),
                                                    pk2(pa[1].x, pa[1].y), pk2(pa[1].z, pa[1].w));
            *(uint4*)&Ts[nb][row][seg + 8] = make_uint4(pk2(pa[2].x, pa[2].y), pk2(pa[2].z, pa[2].w),
                                                        pk2(pa[3].x, pa[3].y), pk2(pa[3].z, pa[3].w));
        }
    }

    const int r = lane >> 2, cpr = (lane & 3) * 2;
#pragma unroll
    for (int i = 0; i < 4; i++)
#pragma unroll
        for (int j = 0; j < 4; j++) {
            int gi = 128 + m0 + i * 16 + r;
            int gj = 128 + n0 + j * 8 + cpr;
            atomicAdd(&g_gram[gi * C_DIM + gj], acc[i][j][0]);
            atomicAdd(&g_gram[gi * C_DIM + gj + 1], acc[i][j][1]);
            atomicAdd(&g_gram[(gi + 8) * C_DIM + gj], acc[i][j][2]);
            atomicAdd(&g_gram[(gi + 8) * C_DIM + gj + 1], acc[i][j][3]);
        }
}

// ---------------- buildA (fused trace): quadrants Q00, Q10 (mirror->Q01), Q11 ----------------
__global__ void buildA_kernel() {
    __shared__ float red[256];
    const float invm = 1.f / (float)M_TOT;
    int t = threadIdx.x;
    {
        float mu = g_mean[t] * invm;
        red[t] = g_gram[t * (C_DIM + 1)] * invm - mu * mu + EPSV;
    }
    __syncthreads();
    for (int s = 128; s > 0; s >>= 1) {
        if (t < s) red[t] += red[t + s];
        __syncthreads();
    }
    float sv = red[0] / (float)C_DIM;
    float invs = 1.f / sv;
    if (blockIdx.x == 0 && t == 0) g_scal[0] = rsqrtf(sv);

    int base = blockIdx.x * 1024 + t * 4;
#pragma unroll
    for (int u = 0; u < 4; u++) {
        int idx = base + u;
        int q = idx >> 14, rr = idx & 16383;
        int i, j;
        if (q == 0)      { i = rr >> 7;         j = rr & 127; }
        else if (q == 1) { i = 128 + (rr >> 7); j = rr & 127; }
        else             { i = 128 + (rr >> 7); j = 128 + (rr & 127); }
        float sig = g_gram[i * C_DIM + j] * invm - (g_mean[i] * invm) * (g_mean[j] * invm);
        if (i == j) sig += EPSV;
        float v = sig * invs - ((i == j) ? 1.f : 0.f);
        g_A[i * C_DIM + j] = v;
        if (q == 1) g_A[j * C_DIM + i] = v;
    }
}

// ---------------- small fp32 64x64-tile GEMM core, K range [kb, ke) ----------------
__device__ __forceinline__ void small_gemm64(const float* __restrict__ A, const float* __restrict__ B,
                                             float acc[4][4], int i0, int j0, int kb, int ke) {
    __shared__ float As[16][68];
    __shared__ float Bs[16][68];
    const int tid = threadIdx.x;
    const int tx = tid & 15, ty = tid >> 4;
    const int arow = tid >> 2, akq = (tid & 3) * 4;
    for (int k0 = kb; k0 < ke; k0 += 16) {
        __syncthreads();
        float4 va = *(const float4*)&A[(i0 + arow) * C_DIM + k0 + akq];
        As[akq + 0][arow] = va.x; As[akq + 1][arow] = va.y;
        As[akq + 2][arow] = va.z; As[akq + 3][arow] = va.w;
        float4 vb = *(const float4*)&B[(k0 + ty) * C_DIM + j0 + tx * 4];
        *(float4*)&Bs[ty][tx * 4] = vb;
        __syncthreads();
#pragma unroll
        for (int k = 0; k < 16; k++) {
            float4 a = *(const float4*)&As[k][ty * 4];
            float4 b = *(const float4*)&Bs[k][tx * 4];
            float av[4] = {a.x, a.y, a.z, a.w};
            float bv[4] = {b.x, b.y, b.z, b.w};
#pragma unroll
            for (int r = 0; r < 4; r++)
#pragma unroll
                for (int c = 0; c < 4; c++) acc[r][c] = fmaf(av[r], bv[c], acc[r][c]);
        }
    }
}

// ---------------- A2 = A@A, split-K x4, atomic accumulate ----------------
__global__ void pgemmA2_kernel() {
    int i0 = blockIdx.y * 64, j0 = blockIdx.x * 64, z = blockIdx.z;
    float acc[4][4] = {};
    small_gemm64(g_A, g_A, acc, i0, j0, z * 64, z * 64 + 64);
    int tx = threadIdx.x & 15, ty = threadIdx.x >> 4;
#pragma unroll
    for (int r = 0; r < 4; r++)
#pragma unroll
        for (int c = 0; c < 4; c++)
            atomicAdd(&g_A2[(i0 + ty * 4 + r) * C_DIM + j0 + tx * 4 + c], acc[r][c]);
}

// ---------------- final: acc = Q@A2 with Q built in the A-tile load ----------------
__global__ void final_gemm_kernel() {
    const float c1 = -0.5f, c2 = 0.375f, c3 = -0.3125f, c4 = 0.2734375f;
    __shared__ float As[16][68];
    __shared__ float Bs[16][68];
    int i0 = blockIdx.y * 64, j0 = blockIdx.x * 64;
    const int tid = threadIdx.x;
    const int tx = tid & 15, ty = tid >> 4;
    const int arow = tid >> 2, akq = (tid & 3) * 4;
    float acc[4][4] = {};

    for (int k0 = 0; k0 < C_DIM; k0 += 16) {
        __syncthreads();
        int gi = i0 + arow, gk = k0 + akq;
        float4 a1 = *(const float4*)&g_A[gi * C_DIM + gk];
        float4 a2 = *(const float4*)&g_A2[gi * C_DIM + gk];
        As[akq + 0][arow] = c3 * a1.x + c4 * a2.x + ((gi == gk + 0) ? c2 : 0.f);
        As[akq + 1][arow] = c3 * a1.y + c4 * a2.y + ((gi == gk + 1) ? c2 : 0.f);
        As[akq + 2][arow] = c3 * a1.z + c4 * a2.z + ((gi == gk + 2) ? c2 : 0.f);
        As[akq + 3][arow] = c3 * a1.w + c4 * a2.w + ((gi == gk + 3) ? c2 : 0.f);
        float4 vb = *(const float4*)&g_A2[(k0 + ty) * C_DIM + j0 + tx * 4];
        *(float4*)&Bs[ty][tx * 4] = vb;
        __syncthreads();
#pragma unroll
        for (int k = 0; k < 16; k++) {
            float4 a = *(const float4*)&As[k][ty * 4];
            float4 b = *(const float4*)&Bs[k][tx * 4];
            float av[4] = {a.x, a.y, a.z, a.w};
            float bv[4] = {b.x, b.y, b.z, b.w};
#pragma unroll
            for (int r = 0; r < 4; r++)
#pragma unroll
                for (int c = 0; c < 4; c++) acc[r][c] = fmaf(av[r], bv[c], acc[r][c]);
        }
    }

    float rs = g_scal[0];
    const float invm = 1.f / (float)M_TOT;
#pragma unroll
    for (int r = 0; r < 4; r++) {
        int gi = i0 + ty * 4 + r;
        float bsum = 0.f;
#pragma unroll
        for (int c = 0; c < 4; c++) {
            int gj = j0 + tx * 4 + c;
            float d = (gi == gj) ? 1.f : 0.f;
            float w = rs * (d + c1 * g_A[gi * C_DIM + gj] + acc[r][c]);
            g_Wb[gi * C_DIM + gj] = __float2bfloat16(w - d);
            bsum += w * (g_mean[gj] * invm);
        }
        atomicAdd(&g_bias[gi], bsum);
    }
}

// ---------------- apply: out = (wm-I)@bf16(X) + X - bias ; M=256 tile (R12 form verbatim) ----------------
#define APPLY_SMEM (2 * 256 * 40 * 2 + 2 * 32 * 136 * 2)   // 58368 bytes
__global__ __launch_bounds__(512, 1) void apply_kernel(const float* __restrict__ X,
                                                       float* __restrict__ out) {
    extern __shared__ __align__(16) char sm[];
    __nv_bfloat16 (*As)[40] = (__nv_bfloat16 (*)[40])sm;
    __nv_bfloat16 (*Bs)[136] = (__nv_bfloat16 (*)[136])(sm + 2 * 256 * 40 * 2);
    const int l0 = blockIdx.x * 128, n = blockIdx.y;
    const int tid = threadIdx.x, wid = tid >> 5, lane = tid & 31;
    const int m0 = (wid >> 2) * 64, n0 = (wid & 3) * 32;
    const int arow = tid >> 1, aseg = (tid & 1) * 16;
    const int brow = tid >> 4, bcol = (tid & 15) * 8;

    const __nv_bfloat16* Ag = g_Wb + arow * C_DIM + aseg;
    const float* Bg = X + ((size_t)(n * C_DIM + brow)) * L_DIM + l0 + bcol;

    float acc[4][4][4];
#pragma unroll
    for (int i = 0; i < 4; i++)
#pragma unroll
        for (int j = 0; j < 4; j++)
#pragma unroll
            for (int r = 0; r < 4; r++) acc[i][j][r] = 0.f;

    uint32_t sA0 = smem_u32(&As[arow][aseg]);
    const uint32_t aStride = 256 * 40 * 2;
    float4 pb0, pb1;

    cp16(sA0, Ag);
    cp16(sA0 + 16, Ag + 8);
    pb0 = *(const float4*)(Bg);
    pb1 = *(const float4*)(Bg + 4);
    cp_commit();
    *(uint4*)&Bs[brow][bcol] = make_uint4(pk2(pb0.x, pb0.y), pk2(pb0.z, pb0.w),
                                          pk2(pb1.x, pb1.y), pk2(pb1.z, pb1.w));

#pragma unroll 1
    for (int c = 0; c < 8; c++) {
        const bool more = (c + 1 < 8);
        if (more) {
            int k0n = (c + 1) * 32;
            int nb = (c + 1) & 1;
            cp16(sA0 + nb * aStride, Ag + k0n);
            cp16(sA0 + nb * aStride + 16, Ag + k0n + 8);
            pb0 = *(const float4*)(Bg + (size_t)k0n * L_DIM);
            pb1 = *(const float4*)(Bg + (size_t)k0n * L_DIM + 4);
            cp_commit();
            cp_wait<1>();
        } else {
            cp_wait<0>();
        }
        __syncthreads();
        const int buf = c & 1;
#pragma unroll
        for (int ks = 0; ks < 2; ks++) {
            uint32_t af[4][4], bq[4][2];
#pragma unroll
            for (int i = 0; i < 4; i++)
                ldsm4(af[i], smem_u32(&As[buf * 256 + m0 + i * 16 + (lane & 15)][ks * 16 + ((lane >> 4) << 3)]));
#pragma unroll
            for (int j = 0; j < 4; j++)
                ldsm2t(bq[j], smem_u32(&Bs[buf * 32 + ks * 16 + (lane & 15)][n0 + j * 8]));
#pragma unroll
            for (int i = 0; i < 4; i++)
#pragma unroll
                for (int j = 0; j < 4; j++) mma_bf16(acc[i][j], af[i], bq[j]);
        }
        if (more) {
            int nb = (c + 1) & 1;
            *(uint4*)&Bs[nb * 32 + brow][bcol] = make_uint4(pk2(pb0.x, pb0.y), pk2(pb0.z, pb0.w),
                                                            pk2(pb1.x, pb1.y), pk2(pb1.z, pb1.w));
        }
    }

    const int r = lane >> 2, cpr = (lane & 3) * 2;
#pragma unroll
    for (int i = 0; i < 4; i++) {
        int c_ = m0 + i * 16 + r;
        float b0 = g_bias[c_], b1 = g_bias[c_ + 8];
        const float* x0 = X + ((size_t)(n * C_DIM + c_)) * L_DIM + l0;
        const float* x1 = x0 + (size_t)8 * L_DIM;
        float* o0 = out + ((size_t)(n * C_DIM + c_)) * L_DIM + l0;
        float* o1 = o0 + (size_t)8 * L_DIM;
#pragma unroll
        for (int j = 0; j < 4; j++) {
            int l = n0 + j * 8 + cpr;
            float2 xv0 = *(const float2*)(x0 + l);
            float2 xv1 = *(const float2*)(x1 + l);
            float2 ov0 = make_float2(acc[i][j][0] + xv0.x - b0, acc[i][j][1] + xv0.y - b0);
            float2 ov1 = make_float2(acc[i][j][2] + xv1.x - b1, acc[i][j][3] + xv1.y - b1);
            *(float2*)(o0 + l) = ov0;
            *(float2*)(o1 + l) = ov1;
        }
    }
}

// ---------------- launch ----------------
extern "C" void kernel_launch(void* const* d_in, const int* in_sizes, int n_in,
                              void* d_out, int out_size) {
    const float* X = (const float*)d_in[0];
    float* out = (float*)d_out;

    cudaFuncSetAttribute(apply_kernel, cudaFuncAttributeMaxDynamicSharedMemorySize, APPLY_SMEM);

    zero_kernel<<<64, 256>>>();
    gramL_kernel<<<dim3(N_DIM, 4), 512>>>(X);

    // gramD is fully independent of gramL: launch with Programmatic Stream
    // Serialization so its CTAs can fill gramL's tail wave. Fallback = normal launch.
    {
        cudaLaunchConfig_t cfg = {};
        cfg.gridDim = dim3(N_DIM, 4);
        cfg.blockDim = dim3(256);
        cfg.dynamicSmemBytes = 0;
        cfg.stream = 0;
        cudaLaunchAttribute attrs[1];
        attrs[0].id = cudaLaunchAttributeProgrammaticStreamSerialization;
        attrs[0].val.programmaticStreamSerializationAllowed = 1;
        cfg.attrs = attrs;
        cfg.numAttrs = 1;
        cudaError_t e = cudaLaunchKernelEx(&cfg, gramD_kernel, X);
        if (e != cudaSuccess) {
            (void)cudaGetLastError();   // clear sticky error
            gramD_kernel<<<dim3(N_DIM, 4), 256>>>(X);
        }
    }

    buildA_kernel<<<48, 256>>>();
    pgemmA2_kernel<<<dim3(4, 4, 4), 256>>>();
    final_gemm_kernel<<<dim3(4, 4), 256>>>();
    apply_kernel<<<dim3(32, N_DIM), 512, APPLY_SMEM>>>(X, out);
}